// round 1
// baseline (speedup 1.0000x reference)
#include <cuda_runtime.h>
#include <cuda_bf16.h>

// Problem constants: b=256, spatial 16x16 (L=256), d_model=d_inner=64,
// N_STATE=24, DT_RANK=24, K=4 directions.
#define BATCH 256
#define L 256
#define D 64
#define NST 24
#define CPROJ 72   // DT_RANK + 2*NST

// ---------------- scratch (device globals; no runtime allocation) ----------
__device__ float g_z[BATCH * L * D];            // gating branch (b,l,e)
__device__ float g_xconv[BATCH * 4 * 64 * 64];  // depthwise conv out (b,c,h,w)
__device__ float g_xt[BATCH * L * D];           // patch-embed+BN out (b,l,d)
__device__ float g_dts[BATCH * 4 * L * D];      // dt (pre-softplus) (b,k,l,d)
__device__ float g_bc[BATCH * 4 * L * 2 * NST]; // interleaved B,C (b,k,l,n,{B,C})
__device__ float g_y[BATCH * 4 * L * D];        // scan outputs (b,k,l,d)

// direction index map: u_k[l] = x_h[map_l(k,l)]
__device__ __forceinline__ int map_l(int k, int l) {
    int lm = (k & 2) ? (255 - l) : l;       // flip for k=2,3
    if (k & 1) lm = ((lm & 15) << 4) | (lm >> 4);  // h/w transpose for k=1,3
    return lm;
}

__device__ __forceinline__ float silu(float x) {
    return x / (1.f + __expf(-x));
}

// ---------------- K1: z = silu(x_in @ in_proj_w^T) -------------------------
// grid (64, B), block (64,4): thread (e, li)
__global__ void k_zproj(const float* __restrict__ xin,
                        const float* __restrict__ w,
                        float* __restrict__ z) {
    __shared__ float ws[64 * 64];  // ws[d*64+e] = w[e*64+d]
    __shared__ float xs[4][64];
    int b = blockIdx.y, lg = blockIdx.x;
    int e = threadIdx.x, li = threadIdx.y;
    int t = li * 64 + e;
    for (int i = t; i < 4096; i += 256) {
        int ee = i >> 6, dd = i & 63;
        ws[dd * 64 + ee] = w[i];
    }
    int l = lg * 4 + li;
    xs[li][e] = xin[(b * 256 + l) * 64 + e];
    __syncthreads();
    float acc = 0.f;
#pragma unroll
    for (int dd = 0; dd < 64; dd++) acc += xs[li][dd] * ws[dd * 64 + e];
    z[(b * 256 + l) * 64 + e] = silu(acc);
}

// ---------------- K2a: rearrange + depthwise 3x3 conv + silu ---------------
// thread per (b,c,h,w); xconv[b,c,h,w]
__global__ void k_dwconv(const float* __restrict__ xin,
                         const float* __restrict__ cw,
                         const float* __restrict__ cb,
                         float* __restrict__ xc) {
    int idx = blockIdx.x * 256 + threadIdx.x;
    if (idx >= BATCH * 4 * 64 * 64) return;
    int w = idx & 63;
    int h = (idx >> 6) & 63;
    int c = (idx >> 12) & 3;
    int b = idx >> 14;
    float wr[9];
#pragma unroll
    for (int i = 0; i < 9; i++) wr[i] = __ldg(&cw[c * 9 + i]);
    float acc = __ldg(&cb[c]);
#pragma unroll
    for (int di = 0; di < 3; di++) {
        int hh = h + di - 1;
        if (hh < 0 || hh > 63) continue;
#pragma unroll
        for (int dj = 0; dj < 3; dj++) {
            int ww = w + dj - 1;
            if (ww < 0 || ww > 63) continue;
            int p = hh >> 2, i2 = hh & 3, q = ww >> 2, j2 = ww & 3;
            // x_rearr[b,c,hh,ww] = x_in[b,p,q, c*16+i2*4+j2]
            float v = xin[((b * 16 + p) * 16 + q) * 64 + c * 16 + i2 * 4 + j2];
            acc += v * wr[di * 3 + dj];
        }
    }
    xc[idx] = silu(acc);
}

// ---------------- K2b: 4x4 stride-4 patch conv + BN (eval) -----------------
// grid (64, B), block (64,4): thread (e, li) -> x_t (b,l,e)
__global__ void k_patch(const float* __restrict__ xc,
                        const float* __restrict__ pw,
                        const float* __restrict__ pb,
                        const float* __restrict__ gam,
                        const float* __restrict__ bet,
                        const float* __restrict__ mn,
                        const float* __restrict__ vr,
                        float* __restrict__ xt) {
    __shared__ float ws[64 * 64];  // ws[m*64+e] = pw[e*64+m], m=c*16+i*4+j
    __shared__ float px[4][64];
    int b = blockIdx.y, lg = blockIdx.x;
    int e = threadIdx.x, li = threadIdx.y;
    int t = li * 64 + e;
    for (int i = t; i < 4096; i += 256) {
        int ee = i >> 6, m = i & 63;
        ws[m * 64 + ee] = pw[i];
    }
    {
        int l = lg * 4 + li;
        int ph = l >> 4, pwd = l & 15;
        int m = e;
        int c = m >> 4, ij = m & 15, i2 = ij >> 2, j2 = ij & 3;
        px[li][m] = xc[((b * 4 + c) * 64 + ph * 4 + i2) * 64 + pwd * 4 + j2];
    }
    __syncthreads();
    float acc = __ldg(&pb[e]);
#pragma unroll
    for (int m = 0; m < 64; m++) acc += px[li][m] * ws[m * 64 + e];
    float sc = __ldg(&gam[e]) * rsqrtf(__ldg(&vr[e]) + 1e-5f);
    float val = (acc - __ldg(&mn[e])) * sc + __ldg(&bet[e]);
    int l = lg * 4 + li;
    xt[(b * 256 + l) * 64 + e] = val;
}

// ---------------- K3: x_dbl projection + dt projection ---------------------
// grid (4, B): block handles (k,b). 256 threads, thread per l.
__global__ void __launch_bounds__(256) k_proj(const float* __restrict__ xt,
                                              const float* __restrict__ xpw,
                                              const float* __restrict__ dtw,
                                              float* __restrict__ dts,
                                              float* __restrict__ bc) {
    __shared__ float dtr_s[256 * 25];  // per-thread dt_rank scratch (padded)
    int k = blockIdx.x, b = blockIdx.y, l = threadIdx.x;
    const float* wk = xpw + k * CPROJ * 64;
    const float* dwk = dtw + k * 64 * NST;
    int lm = map_l(k, l);
    float xcol[64];
    const float4* xp = (const float4*)(xt + (b * 256 + lm) * 64);
#pragma unroll
    for (int i = 0; i < 16; i++) {
        float4 v = __ldg(xp + i);
        xcol[4 * i] = v.x; xcol[4 * i + 1] = v.y;
        xcol[4 * i + 2] = v.z; xcol[4 * i + 3] = v.w;
    }
    int base = (b * 4 + k) * 256 + l;
    float* bco = bc + base * (2 * NST);
#pragma unroll 4
    for (int c = 0; c < CPROJ; c++) {
        const float4* wp = (const float4*)(wk + c * 64);
        float acc = 0.f;
#pragma unroll
        for (int i = 0; i < 16; i++) {
            float4 wv = __ldg(wp + i);
            acc += xcol[4 * i] * wv.x + xcol[4 * i + 1] * wv.y +
                   xcol[4 * i + 2] * wv.z + xcol[4 * i + 3] * wv.w;
        }
        if (c < NST) dtr_s[l * 25 + c] = acc;
        else if (c < 2 * NST) bco[(c - NST) * 2] = acc;        // B
        else bco[(c - 2 * NST) * 2 + 1] = acc;                 // C
    }
    float dtr[NST];
#pragma unroll
    for (int r = 0; r < NST; r++) dtr[r] = dtr_s[l * 25 + r];
    float* dto = dts + base * 64;
#pragma unroll 2
    for (int d = 0; d < 64; d++) {
        const float* dw = dwk + d * NST;
        float acc = 0.f;
#pragma unroll
        for (int r = 0; r < NST; r++) acc += dtr[r] * __ldg(&dw[r]);
        dto[d] = acc;
    }
}

// ---------------- K4: selective scan ----------------------------------------
// grid (B), block 256: thread = (k,d), k = tid>>6, d = tid&63.
// State h[24] and A row in registers; B/C chunk-staged in smem as float2.
__global__ void __launch_bounds__(256) k_scan(const float* __restrict__ xt,
                                              const float* __restrict__ dts,
                                              const float* __restrict__ bc,
                                              const float* __restrict__ alog,
                                              const float* __restrict__ dbias,
                                              const float* __restrict__ Dsv,
                                              float* __restrict__ yg) {
    __shared__ float bcs[4][16 * 2 * NST];  // 12 KB
    int b = blockIdx.x;
    int k = threadIdx.x >> 6, d = threadIdx.x & 63;
    int kd = k * 64 + d;
    float a[NST], h[NST];
#pragma unroll
    for (int n = 0; n < NST; n++) {
        a[n] = -__expf(__ldg(&alog[kd * NST + n]));
        h[n] = 0.f;
    }
    float bias = __ldg(&dbias[kd]);
    float Dv = __ldg(&Dsv[kd]);
    int kb = (b * 4 + k) * 256;
    const float* dtp = dts + kb * 64;
    float* yp = yg + kb * 64;
    const float* bcp = bc + kb * (2 * NST);
    for (int l0 = 0; l0 < 256; l0 += 16) {
        __syncthreads();
#pragma unroll
        for (int j = 0; j < 12; j++)
            bcs[k][j * 64 + d] = bcp[l0 * (2 * NST) + j * 64 + d];
        __syncthreads();
#pragma unroll 1
        for (int i = 0; i < 16; i++) {
            int l = l0 + i;
            float dtv = dtp[l * 64 + d];
            int lm = map_l(k, l);
            float u = __ldg(&xt[(b * 256 + lm) * 64 + d]);
            float x = dtv + bias;
            float delta = (x > 20.f) ? x : log1pf(__expf(x));
            float du = delta * u;
            float y = 0.f;
            const float2* bcrow = (const float2*)&bcs[k][i * 2 * NST];
#pragma unroll
            for (int n = 0; n < NST; n++) {
                float2 bcv = bcrow[n];
                float dA = __expf(delta * a[n]);
                h[n] = dA * h[n] + du * bcv.x;
                y += h[n] * bcv.y;
            }
            yp[l * 64 + d] = y + Dv * u;
        }
    }
}

// ---------------- K5: combine dirs + LayerNorm + gate + out_proj -----------
// grid (B), block 256: thread per l. 64-float row lives in registers.
__global__ void __launch_bounds__(256) k_final(const float* __restrict__ yg,
                                               const float* __restrict__ zg,
                                               const float* __restrict__ lng,
                                               const float* __restrict__ lnb,
                                               const float* __restrict__ wo,
                                               float* __restrict__ out) {
    __shared__ float ws[64 * 64];  // ws[e*64+d] = wo[d*64+e]
    __shared__ float gs[64], bs[64];
    int b = blockIdx.x, l = threadIdx.x;
    for (int i = l; i < 4096; i += 256) {
        int dd = i >> 6, ee = i & 63;
        ws[ee * 64 + dd] = wo[i];
    }
    if (l < 64) { gs[l] = lng[l]; bs[l] = lnb[l]; }
    __syncthreads();
    int l1 = ((l & 15) << 4) | (l >> 4);
    int b4 = b * 4;
    const float4* y0 = (const float4*)(yg + ((b4 + 0) * 256 + l) * 64);
    const float4* y1 = (const float4*)(yg + ((b4 + 1) * 256 + l1) * 64);
    const float4* y2 = (const float4*)(yg + ((b4 + 2) * 256 + (255 - l)) * 64);
    const float4* y3 = (const float4*)(yg + ((b4 + 3) * 256 + (255 - l1)) * 64);
    float yv[64];
    float mu = 0.f;
#pragma unroll
    for (int i = 0; i < 16; i++) {
        float4 v0 = y0[i], v1 = y1[i], v2 = y2[i], v3 = y3[i];
        yv[4 * i + 0] = v0.x + v1.x + v2.x + v3.x;
        yv[4 * i + 1] = v0.y + v1.y + v2.y + v3.y;
        yv[4 * i + 2] = v0.z + v1.z + v2.z + v3.z;
        yv[4 * i + 3] = v0.w + v1.w + v2.w + v3.w;
        mu += yv[4 * i] + yv[4 * i + 1] + yv[4 * i + 2] + yv[4 * i + 3];
    }
    mu *= (1.f / 64.f);
    float var = 0.f;
#pragma unroll
    for (int e = 0; e < 64; e++) {
        float t = yv[e] - mu;
        var += t * t;
    }
    var *= (1.f / 64.f);
    float rs = rsqrtf(var + 1e-5f);
    const float4* zp = (const float4*)(zg + (b * 256 + l) * 64);
#pragma unroll
    for (int i = 0; i < 16; i++) {
        float4 zv = zp[i];
        yv[4 * i + 0] = ((yv[4 * i + 0] - mu) * rs * gs[4 * i + 0] + bs[4 * i + 0]) * zv.x;
        yv[4 * i + 1] = ((yv[4 * i + 1] - mu) * rs * gs[4 * i + 1] + bs[4 * i + 1]) * zv.y;
        yv[4 * i + 2] = ((yv[4 * i + 2] - mu) * rs * gs[4 * i + 2] + bs[4 * i + 2]) * zv.z;
        yv[4 * i + 3] = ((yv[4 * i + 3] - mu) * rs * gs[4 * i + 3] + bs[4 * i + 3]) * zv.w;
    }
    float4* op = (float4*)(out + (b * 256 + l) * 64);
#pragma unroll 1
    for (int dc = 0; dc < 16; dc++) {
        float4 acc = {0.f, 0.f, 0.f, 0.f};
#pragma unroll
        for (int e = 0; e < 64; e++) {
            float4 w4 = *(const float4*)&ws[e * 64 + dc * 4];
            acc.x += yv[e] * w4.x;
            acc.y += yv[e] * w4.y;
            acc.z += yv[e] * w4.z;
            acc.w += yv[e] * w4.w;
        }
        op[dc] = acc;
    }
}

// ---------------- launch -----------------------------------------------------
extern "C" void kernel_launch(void* const* d_in, const int* in_sizes, int n_in,
                              void* d_out, int out_size) {
    const float* x_in   = (const float*)d_in[0];
    const float* ipw    = (const float*)d_in[1];
    const float* conv_w = (const float*)d_in[2];
    const float* conv_b = (const float*)d_in[3];
    const float* patch_w= (const float*)d_in[4];
    const float* patch_b= (const float*)d_in[5];
    const float* bn_g   = (const float*)d_in[6];
    const float* bn_b   = (const float*)d_in[7];
    const float* bn_m   = (const float*)d_in[8];
    const float* bn_v   = (const float*)d_in[9];
    const float* xpw    = (const float*)d_in[10];
    const float* dtw    = (const float*)d_in[11];
    const float* dtb    = (const float*)d_in[12];
    const float* alog   = (const float*)d_in[13];
    const float* Dsv    = (const float*)d_in[14];
    const float* lng    = (const float*)d_in[15];
    const float* lnb    = (const float*)d_in[16];
    const float* wo     = (const float*)d_in[17];
    float* out = (float*)d_out;

    float *zg, *xc, *xt, *dts, *bc, *yg;
    cudaGetSymbolAddress((void**)&zg,  g_z);
    cudaGetSymbolAddress((void**)&xc,  g_xconv);
    cudaGetSymbolAddress((void**)&xt,  g_xt);
    cudaGetSymbolAddress((void**)&dts, g_dts);
    cudaGetSymbolAddress((void**)&bc,  g_bc);
    cudaGetSymbolAddress((void**)&yg,  g_y);

    dim3 blk64_4(64, 4);
    k_zproj<<<dim3(64, BATCH), blk64_4>>>(x_in, ipw, zg);
    k_dwconv<<<(BATCH * 4 * 64 * 64) / 256, 256>>>(x_in, conv_w, conv_b, xc);
    k_patch<<<dim3(64, BATCH), blk64_4>>>(xc, patch_w, patch_b,
                                          bn_g, bn_b, bn_m, bn_v, xt);
    k_proj<<<dim3(4, BATCH), 256>>>(xt, xpw, dtw, dts, bc);
    k_scan<<<BATCH, 256>>>(xt, dts, bc, alog, dtb, Dsv, yg);
    k_final<<<BATCH, 256>>>(yg, zg, lng, lnb, wo, out);
}

// round 2
// speedup vs baseline: 2.3145x; 2.3145x over previous
#include <cuda_runtime.h>
#include <cuda_bf16.h>

#define BATCH 256
#define L 256
#define D 64
#define NST 24
#define CPROJ 72   // DT_RANK + 2*NST

typedef unsigned long long u64;

// ---------------- scratch ----------------------------------------------------
__device__ float g_z[BATCH * L * D];            // (b,l,e)
__device__ float g_xconv[BATCH * 4 * 64 * 64];  // (b,c,h,w)
__device__ float g_xt[BATCH * L * D];           // (b,l,d)
__device__ float g_dts[BATCH * 4 * D * L];      // (b,k,d,l)   TRANSPOSED
__device__ float g_bc[BATCH * 4 * 48 * L];      // (b,k,j,l)   j: 0..23=B, 24..47=C
__device__ float g_y[BATCH * 4 * L * D];        // (b,k,l,d)

__device__ __forceinline__ int map_l(int k, int l) {
    int lm = (k & 2) ? (255 - l) : l;
    if (k & 1) lm = ((lm & 15) << 4) | (lm >> 4);
    return lm;
}
__device__ __forceinline__ float silu(float x) { return x / (1.f + __expf(-x)); }

// f32x2 packed helpers
__device__ __forceinline__ u64 pk2(float lo, float hi) {
    u64 r; asm("mov.b64 %0,{%1,%2};" : "=l"(r) : "f"(lo), "f"(hi)); return r;
}
__device__ __forceinline__ void unpk2(float& lo, float& hi, u64 v) {
    asm("mov.b64 {%0,%1},%2;" : "=f"(lo), "=f"(hi) : "l"(v));
}
__device__ __forceinline__ u64 mul2(u64 a, u64 b) {
    u64 r; asm("mul.rn.f32x2 %0,%1,%2;" : "=l"(r) : "l"(a), "l"(b)); return r;
}
__device__ __forceinline__ u64 fma2(u64 a, u64 b, u64 c) {
    u64 r; asm("fma.rn.f32x2 %0,%1,%2,%3;" : "=l"(r) : "l"(a), "l"(b), "l"(c)); return r;
}

// ---------------- K1: z = silu(x_in @ in_proj_w^T) -------------------------
// grid (16, B), block (64,4). Block handles 16 l-rows.
__global__ void k_zproj(const float* __restrict__ xin,
                        const float* __restrict__ w,
                        float* __restrict__ z) {
    __shared__ float ws[64 * 64];   // ws[d*64+e] = w[e*64+d]
    __shared__ float xs[16][64];
    int b = blockIdx.y, lg = blockIdx.x;
    int e = threadIdx.x, li = threadIdx.y;
    int t = li * 64 + e;
    for (int i = t; i < 4096; i += 256) ws[(i & 63) * 64 + (i >> 6)] = w[i];
    {
        int row = t >> 4, m = t & 15;
        ((float4*)xs[row])[m] =
            ((const float4*)(xin + (b * 256 + lg * 16 + row) * 64))[m];
    }
    __syncthreads();
    float acc0 = 0.f, acc1 = 0.f, acc2 = 0.f, acc3 = 0.f;
    int r0 = li * 4;
#pragma unroll
    for (int d4 = 0; d4 < 16; d4++) {
        float4 x0 = ((const float4*)xs[r0 + 0])[d4];
        float4 x1 = ((const float4*)xs[r0 + 1])[d4];
        float4 x2 = ((const float4*)xs[r0 + 2])[d4];
        float4 x3 = ((const float4*)xs[r0 + 3])[d4];
#pragma unroll
        for (int dd = 0; dd < 4; dd++) {
            float wv = ws[(d4 * 4 + dd) * 64 + e];
            float v0 = dd == 0 ? x0.x : dd == 1 ? x0.y : dd == 2 ? x0.z : x0.w;
            float v1 = dd == 0 ? x1.x : dd == 1 ? x1.y : dd == 2 ? x1.z : x1.w;
            float v2 = dd == 0 ? x2.x : dd == 1 ? x2.y : dd == 2 ? x2.z : x2.w;
            float v3 = dd == 0 ? x3.x : dd == 1 ? x3.y : dd == 2 ? x3.z : x3.w;
            acc0 += v0 * wv; acc1 += v1 * wv; acc2 += v2 * wv; acc3 += v3 * wv;
        }
    }
    int lb = (b * 256 + lg * 16 + r0) * 64 + e;
    z[lb]           = silu(acc0);
    z[lb + 64]      = silu(acc1);
    z[lb + 128]     = silu(acc2);
    z[lb + 192]     = silu(acc3);
}

// ---------------- K2a: rearrange + depthwise 3x3 conv + silu ---------------
__global__ void k_dwconv(const float* __restrict__ xin,
                         const float* __restrict__ cw,
                         const float* __restrict__ cb,
                         float* __restrict__ xc) {
    int idx = blockIdx.x * 256 + threadIdx.x;
    if (idx >= BATCH * 4 * 64 * 64) return;
    int w = idx & 63;
    int h = (idx >> 6) & 63;
    int c = (idx >> 12) & 3;
    int b = idx >> 14;
    float wr[9];
#pragma unroll
    for (int i = 0; i < 9; i++) wr[i] = __ldg(&cw[c * 9 + i]);
    float acc = __ldg(&cb[c]);
#pragma unroll
    for (int di = 0; di < 3; di++) {
        int hh = h + di - 1;
        if (hh < 0 || hh > 63) continue;
#pragma unroll
        for (int dj = 0; dj < 3; dj++) {
            int ww = w + dj - 1;
            if (ww < 0 || ww > 63) continue;
            int p = hh >> 2, i2 = hh & 3, q = ww >> 2, j2 = ww & 3;
            float v = xin[((b * 16 + p) * 16 + q) * 64 + c * 16 + i2 * 4 + j2];
            acc += v * wr[di * 3 + dj];
        }
    }
    xc[idx] = silu(acc);
}

// ---------------- K2b: patch conv + BN --------------------------------------
// grid (16, B), block (64,4): 16 l-rows per block.
__global__ void k_patch(const float* __restrict__ xc,
                        const float* __restrict__ pw,
                        const float* __restrict__ pb,
                        const float* __restrict__ gam,
                        const float* __restrict__ bet,
                        const float* __restrict__ mn,
                        const float* __restrict__ vr,
                        float* __restrict__ xt) {
    __shared__ float ws[64 * 64];   // ws[m*64+e] = pw[e*64+m]
    __shared__ float px[16][64];
    int b = blockIdx.y, lg = blockIdx.x;
    int e = threadIdx.x, li = threadIdx.y;
    int t = li * 64 + e;
    for (int i = t; i < 4096; i += 256) ws[(i & 63) * 64 + (i >> 6)] = pw[i];
    for (int i = t; i < 1024; i += 256) {
        int row = i >> 6, m = i & 63;
        int l = lg * 16 + row;
        int ph = l >> 4, pwd = l & 15;
        int c = m >> 4, ij = m & 15, i2 = ij >> 2, j2 = ij & 3;
        px[row][m] = xc[((b * 4 + c) * 64 + ph * 4 + i2) * 64 + pwd * 4 + j2];
    }
    __syncthreads();
    float acc0 = 0.f, acc1 = 0.f, acc2 = 0.f, acc3 = 0.f;
    int r0 = li * 4;
#pragma unroll
    for (int m4 = 0; m4 < 16; m4++) {
        float4 x0 = ((const float4*)px[r0 + 0])[m4];
        float4 x1 = ((const float4*)px[r0 + 1])[m4];
        float4 x2 = ((const float4*)px[r0 + 2])[m4];
        float4 x3 = ((const float4*)px[r0 + 3])[m4];
#pragma unroll
        for (int dd = 0; dd < 4; dd++) {
            float wv = ws[(m4 * 4 + dd) * 64 + e];
            float v0 = dd == 0 ? x0.x : dd == 1 ? x0.y : dd == 2 ? x0.z : x0.w;
            float v1 = dd == 0 ? x1.x : dd == 1 ? x1.y : dd == 2 ? x1.z : x1.w;
            float v2 = dd == 0 ? x2.x : dd == 1 ? x2.y : dd == 2 ? x2.z : x2.w;
            float v3 = dd == 0 ? x3.x : dd == 1 ? x3.y : dd == 2 ? x3.z : x3.w;
            acc0 += v0 * wv; acc1 += v1 * wv; acc2 += v2 * wv; acc3 += v3 * wv;
        }
    }
    float sc = __ldg(&gam[e]) * rsqrtf(__ldg(&vr[e]) + 1e-5f);
    float pbv = __ldg(&pb[e]), mnv = __ldg(&mn[e]), btv = __ldg(&bet[e]);
    int lb = (b * 256 + lg * 16 + r0) * 64 + e;
    xt[lb]       = (acc0 + pbv - mnv) * sc + btv;
    xt[lb + 64]  = (acc1 + pbv - mnv) * sc + btv;
    xt[lb + 128] = (acc2 + pbv - mnv) * sc + btv;
    xt[lb + 192] = (acc3 + pbv - mnv) * sc + btv;
}

// ---------------- K3: x_dbl + dt projections (weights in smem, coalesced out)
// grid (4, B), 256 threads (thread per l).
__global__ void __launch_bounds__(256, 2) k_proj(const float* __restrict__ xt,
                                                 const float* __restrict__ xpw,
                                                 const float* __restrict__ dtw,
                                                 float* __restrict__ dts,
                                                 float* __restrict__ bc) {
    __shared__ float ws[CPROJ * 64];   // 18 KB
    __shared__ float dws[64 * NST];    // 6 KB
    int k = blockIdx.x, b = blockIdx.y, l = threadIdx.x;
    const float* wk = xpw + k * CPROJ * 64;
    for (int i = l; i < CPROJ * 64; i += 256) ws[i] = wk[i];
    const float* dwk = dtw + k * 64 * NST;
    for (int i = l; i < 64 * NST; i += 256) dws[i] = dwk[i];
    __syncthreads();

    int lm = map_l(k, l);
    float xcol[64];
    const float4* xp = (const float4*)(xt + (b * 256 + lm) * 64);
#pragma unroll
    for (int i = 0; i < 16; i++) {
        float4 v = __ldg(xp + i);
        xcol[4 * i] = v.x; xcol[4 * i + 1] = v.y;
        xcol[4 * i + 2] = v.z; xcol[4 * i + 3] = v.w;
    }
    int base = b * 4 + k;
    float dtr[NST];
#pragma unroll
    for (int c = 0; c < NST; c++) {
        const float4* wp = (const float4*)(ws + c * 64);
        float acc = 0.f;
#pragma unroll
        for (int i = 0; i < 16; i++) {
            float4 wv = wp[i];
            acc += xcol[4 * i] * wv.x + xcol[4 * i + 1] * wv.y +
                   xcol[4 * i + 2] * wv.z + xcol[4 * i + 3] * wv.w;
        }
        dtr[c] = acc;
    }
    float* bco = bc + base * 48 * 256;
#pragma unroll 4
    for (int c = NST; c < CPROJ; c++) {
        const float4* wp = (const float4*)(ws + c * 64);
        float acc = 0.f;
#pragma unroll
        for (int i = 0; i < 16; i++) {
            float4 wv = wp[i];
            acc += xcol[4 * i] * wv.x + xcol[4 * i + 1] * wv.y +
                   xcol[4 * i + 2] * wv.z + xcol[4 * i + 3] * wv.w;
        }
        bco[(c - NST) * 256 + l] = acc;   // coalesced
    }
    float* dto = dts + base * 64 * 256;
#pragma unroll 4
    for (int d = 0; d < 64; d++) {
        const float4* dw = (const float4*)(dws + d * NST);
        float acc = 0.f;
#pragma unroll
        for (int i = 0; i < 6; i++) {
            float4 wv = dw[i];
            acc += dtr[4 * i] * wv.x + dtr[4 * i + 1] * wv.y +
                   dtr[4 * i + 2] * wv.z + dtr[4 * i + 3] * wv.w;
        }
        dto[d * 256 + l] = acc;           // coalesced
    }
}

// ---------------- K4: selective scan (f32x2 packed, exp-chain fast path) ----
// grid (4, B), block 64 (thread per d).
__global__ void __launch_bounds__(64) k_scan(const float* __restrict__ xt,
                                             const float* __restrict__ dts,
                                             const float* __restrict__ bc,
                                             const float* __restrict__ alog,
                                             const float* __restrict__ dbias,
                                             const float* __restrict__ Dsv,
                                             float* __restrict__ yg) {
    __shared__ float sdt[64][17];
    __shared__ float sbc[16][48];
    int k = blockIdx.x, b = blockIdx.y;
    int d = threadIdx.x;
    int kd = k * 64 + d;

    float a[NST];
#pragma unroll
    for (int n = 0; n < NST; n++) a[n] = -__expf(__ldg(&alog[kd * NST + n]));
    float a0 = a[0];
    bool chain = (a0 != 0.f);
#pragma unroll
    for (int n = 1; n < NST; n++)
        chain = chain && (fabsf(a[n] - (float)(n + 1) * a0) <= 1e-4f * fabsf(a[n]));

    float bias = __ldg(&dbias[kd]);
    float Dv = __ldg(&Dsv[kd]);
    int kb = b * 4 + k;
    const float* dtp = dts + kb * 64 * 256;   // [d][l]
    const float* bcp = bc + kb * 48 * 256;    // [j][l]
    const float* xrow = xt + b * 256 * 64;
    float* yp = yg + kb * 256 * 64;           // [l][d]

    u64 h2[12];
    float hs[NST];
#pragma unroll
    for (int p = 0; p < 12; p++) h2[p] = pk2(0.f, 0.f);
#pragma unroll
    for (int n = 0; n < NST; n++) hs[n] = 0.f;

    for (int l0 = 0; l0 < 256; l0 += 16) {
        __syncthreads();
        {
            const float4* src = (const float4*)(dtp + d * 256 + l0);
            float4 v0 = src[0], v1 = src[1], v2 = src[2], v3 = src[3];
            sdt[d][0] = v0.x; sdt[d][1] = v0.y; sdt[d][2] = v0.z; sdt[d][3] = v0.w;
            sdt[d][4] = v1.x; sdt[d][5] = v1.y; sdt[d][6] = v1.z; sdt[d][7] = v1.w;
            sdt[d][8] = v2.x; sdt[d][9] = v2.y; sdt[d][10] = v2.z; sdt[d][11] = v2.w;
            sdt[d][12] = v3.x; sdt[d][13] = v3.y; sdt[d][14] = v3.z; sdt[d][15] = v3.w;
        }
#pragma unroll
        for (int m = 0; m < 12; m++) {
            int idx = d * 12 + m;
            int j = idx >> 4, i = idx & 15;
            sbc[i][j] = bcp[j * 256 + l0 + i];
        }
        __syncthreads();
        if (chain) {
#pragma unroll 2
            for (int i = 0; i < 16; i++) {
                int l = l0 + i;
                float dtv = sdt[d][i];
                float xv = dtv + bias;
                float delta = (xv > 15.f) ? xv : log1pf(__expf(xv));
                int lm = map_l(k, l);
                float u = __ldg(&xrow[lm * 64 + d]);
                float du = delta * u;
                float q = __expf(delta * a0);
                float q2 = q * q;
                u64 dA = pk2(q, q2);
                u64 qq = pk2(q2, q2);
                u64 du2 = pk2(du, du);
                u64 y2 = pk2(0.f, 0.f);
#pragma unroll
                for (int p = 0; p < 12; p++) {
                    u64 B2 = *(const u64*)&sbc[i][2 * p];
                    u64 C2 = *(const u64*)&sbc[i][24 + 2 * p];
                    u64 t = mul2(du2, B2);
                    h2[p] = fma2(dA, h2[p], t);
                    y2 = fma2(h2[p], C2, y2);
                    if (p < 11) dA = mul2(dA, qq);
                }
                float ylo, yhi;
                unpk2(ylo, yhi, y2);
                yp[l * 64 + d] = ylo + yhi + Dv * u;
            }
        } else {
#pragma unroll 1
            for (int i = 0; i < 16; i++) {
                int l = l0 + i;
                float dtv = sdt[d][i];
                float xv = dtv + bias;
                float delta = (xv > 15.f) ? xv : log1pf(__expf(xv));
                int lm = map_l(k, l);
                float u = __ldg(&xrow[lm * 64 + d]);
                float du = delta * u;
                float y = 0.f;
#pragma unroll
                for (int n = 0; n < NST; n++) {
                    float dAv = __expf(delta * a[n]);
                    hs[n] = dAv * hs[n] + du * sbc[i][n];
                    y += hs[n] * sbc[i][24 + n];
                }
                yp[l * 64 + d] = y + Dv * u;
            }
        }
    }
}

// ---------------- K5: combine + LN + gate + out_proj ------------------------
__global__ void __launch_bounds__(256) k_final(const float* __restrict__ yg,
                                               const float* __restrict__ zg,
                                               const float* __restrict__ lng,
                                               const float* __restrict__ lnb,
                                               const float* __restrict__ wo,
                                               float* __restrict__ out) {
    __shared__ float ws[64 * 64];
    __shared__ float gs[64], bs[64];
    int b = blockIdx.x, l = threadIdx.x;
    for (int i = l; i < 4096; i += 256) {
        int dd = i >> 6, ee = i & 63;
        ws[ee * 64 + dd] = wo[i];
    }
    if (l < 64) { gs[l] = lng[l]; bs[l] = lnb[l]; }
    __syncthreads();
    int l1 = ((l & 15) << 4) | (l >> 4);
    int b4 = b * 4;
    const float4* y0 = (const float4*)(yg + ((b4 + 0) * 256 + l) * 64);
    const float4* y1 = (const float4*)(yg + ((b4 + 1) * 256 + l1) * 64);
    const float4* y2 = (const float4*)(yg + ((b4 + 2) * 256 + (255 - l)) * 64);
    const float4* y3 = (const float4*)(yg + ((b4 + 3) * 256 + (255 - l1)) * 64);
    float yv[64];
    float mu = 0.f;
#pragma unroll
    for (int i = 0; i < 16; i++) {
        float4 v0 = y0[i], v1 = y1[i], v2 = y2[i], v3 = y3[i];
        yv[4 * i + 0] = v0.x + v1.x + v2.x + v3.x;
        yv[4 * i + 1] = v0.y + v1.y + v2.y + v3.y;
        yv[4 * i + 2] = v0.z + v1.z + v2.z + v3.z;
        yv[4 * i + 3] = v0.w + v1.w + v2.w + v3.w;
        mu += yv[4 * i] + yv[4 * i + 1] + yv[4 * i + 2] + yv[4 * i + 3];
    }
    mu *= (1.f / 64.f);
    float var = 0.f;
#pragma unroll
    for (int e = 0; e < 64; e++) {
        float t = yv[e] - mu;
        var += t * t;
    }
    var *= (1.f / 64.f);
    float rs = rsqrtf(var + 1e-5f);
    const float4* zp = (const float4*)(zg + (b * 256 + l) * 64);
#pragma unroll
    for (int i = 0; i < 16; i++) {
        float4 zv = zp[i];
        yv[4 * i + 0] = ((yv[4 * i + 0] - mu) * rs * gs[4 * i + 0] + bs[4 * i + 0]) * zv.x;
        yv[4 * i + 1] = ((yv[4 * i + 1] - mu) * rs * gs[4 * i + 1] + bs[4 * i + 1]) * zv.y;
        yv[4 * i + 2] = ((yv[4 * i + 2] - mu) * rs * gs[4 * i + 2] + bs[4 * i + 2]) * zv.z;
        yv[4 * i + 3] = ((yv[4 * i + 3] - mu) * rs * gs[4 * i + 3] + bs[4 * i + 3]) * zv.w;
    }
    float4* op = (float4*)(out + (b * 256 + l) * 64);
#pragma unroll 1
    for (int dc = 0; dc < 16; dc++) {
        float4 acc = {0.f, 0.f, 0.f, 0.f};
#pragma unroll
        for (int e = 0; e < 64; e++) {
            float4 w4 = *(const float4*)&ws[e * 64 + dc * 4];
            acc.x += yv[e] * w4.x;
            acc.y += yv[e] * w4.y;
            acc.z += yv[e] * w4.z;
            acc.w += yv[e] * w4.w;
        }
        op[dc] = acc;
    }
}

// ---------------- launch -----------------------------------------------------
extern "C" void kernel_launch(void* const* d_in, const int* in_sizes, int n_in,
                              void* d_out, int out_size) {
    const float* x_in   = (const float*)d_in[0];
    const float* ipw    = (const float*)d_in[1];
    const float* conv_w = (const float*)d_in[2];
    const float* conv_b = (const float*)d_in[3];
    const float* patch_w= (const float*)d_in[4];
    const float* patch_b= (const float*)d_in[5];
    const float* bn_g   = (const float*)d_in[6];
    const float* bn_b   = (const float*)d_in[7];
    const float* bn_m   = (const float*)d_in[8];
    const float* bn_v   = (const float*)d_in[9];
    const float* xpw    = (const float*)d_in[10];
    const float* dtw    = (const float*)d_in[11];
    const float* dtb    = (const float*)d_in[12];
    const float* alog   = (const float*)d_in[13];
    const float* Dsv    = (const float*)d_in[14];
    const float* lng    = (const float*)d_in[15];
    const float* lnb    = (const float*)d_in[16];
    const float* wo     = (const float*)d_in[17];
    float* out = (float*)d_out;

    float *zg, *xc, *xt, *dts, *bc, *yg;
    cudaGetSymbolAddress((void**)&zg,  g_z);
    cudaGetSymbolAddress((void**)&xc,  g_xconv);
    cudaGetSymbolAddress((void**)&xt,  g_xt);
    cudaGetSymbolAddress((void**)&dts, g_dts);
    cudaGetSymbolAddress((void**)&bc,  g_bc);
    cudaGetSymbolAddress((void**)&yg,  g_y);

    dim3 blk64_4(64, 4);
    k_zproj<<<dim3(16, BATCH), blk64_4>>>(x_in, ipw, zg);
    k_dwconv<<<(BATCH * 4 * 64 * 64) / 256, 256>>>(x_in, conv_w, conv_b, xc);
    k_patch<<<dim3(16, BATCH), blk64_4>>>(xc, patch_w, patch_b,
                                          bn_g, bn_b, bn_m, bn_v, xt);
    k_proj<<<dim3(4, BATCH), 256>>>(xt, xpw, dtw, dts, bc);
    k_scan<<<dim3(4, BATCH), 64>>>(xt, dts, bc, alog, dtb, Dsv, yg);
    k_final<<<BATCH, 256>>>(yg, zg, lng, lnb, wo, out);
}

// round 3
// speedup vs baseline: 3.0794x; 1.3305x over previous
#include <cuda_runtime.h>
#include <cuda_bf16.h>

#define BATCH 256
#define L 256
#define D 64
#define NST 24
#define CPROJ 72   // DT_RANK + 2*NST

typedef unsigned long long u64;

// ---------------- scratch ----------------------------------------------------
__device__ float g_z[BATCH * L * D];            // (b,l,e)
__device__ float g_xconv[BATCH * 4 * 64 * 64];  // (b,c,h,w)
__device__ float g_xt[BATCH * L * D];           // (b,l,d)
__device__ float g_dts[BATCH * 4 * D * L];      // (b,k,d,l)
__device__ float g_bc[BATCH * 4 * 48 * L];      // (b,k,j,l)  j:0..23=B, 24..47=C
__device__ float g_y[BATCH * 4 * L * D];        // (b,k,l,d)

__device__ __forceinline__ int map_l(int k, int l) {
    int lm = (k & 2) ? (255 - l) : l;
    if (k & 1) lm = ((lm & 15) << 4) | (lm >> 4);
    return lm;
}
__device__ __forceinline__ float silu(float x) { return x / (1.f + __expf(-x)); }

// f32x2 packed helpers
__device__ __forceinline__ u64 pk2(float lo, float hi) {
    u64 r; asm("mov.b64 %0,{%1,%2};" : "=l"(r) : "f"(lo), "f"(hi)); return r;
}
__device__ __forceinline__ void unpk2(float& lo, float& hi, u64 v) {
    asm("mov.b64 {%0,%1},%2;" : "=f"(lo), "=f"(hi) : "l"(v));
}
__device__ __forceinline__ u64 mul2(u64 a, u64 b) {
    u64 r; asm("mul.rn.f32x2 %0,%1,%2;" : "=l"(r) : "l"(a), "l"(b)); return r;
}
__device__ __forceinline__ u64 fma2(u64 a, u64 b, u64 c) {
    u64 r; asm("fma.rn.f32x2 %0,%1,%2,%3;" : "=l"(r) : "l"(a), "l"(b), "l"(c)); return r;
}

// ---------------- K1: z = silu(x_in @ in_proj_w^T) -------------------------
__global__ void k_zproj(const float* __restrict__ xin,
                        const float* __restrict__ w,
                        float* __restrict__ z) {
    __shared__ __align__(16) float ws[64 * 65];   // ws[d*65+e], padded
    __shared__ __align__(16) float xs[16][64];
    int b = blockIdx.y, lg = blockIdx.x;
    int e = threadIdx.x, li = threadIdx.y;
    int t = li * 64 + e;
    for (int i = t; i < 4096; i += 256) ws[(i & 63) * 65 + (i >> 6)] = w[i];
    {
        int row = t >> 4, m = t & 15;
        ((float4*)xs[row])[m] =
            ((const float4*)(xin + (b * 256 + lg * 16 + row) * 64))[m];
    }
    __syncthreads();
    float acc0 = 0.f, acc1 = 0.f, acc2 = 0.f, acc3 = 0.f;
    int r0 = li * 4;
#pragma unroll
    for (int d4 = 0; d4 < 16; d4++) {
        float4 x0 = ((const float4*)xs[r0 + 0])[d4];
        float4 x1 = ((const float4*)xs[r0 + 1])[d4];
        float4 x2 = ((const float4*)xs[r0 + 2])[d4];
        float4 x3 = ((const float4*)xs[r0 + 3])[d4];
#pragma unroll
        for (int dd = 0; dd < 4; dd++) {
            float wv = ws[(d4 * 4 + dd) * 65 + e];
            float v0 = dd == 0 ? x0.x : dd == 1 ? x0.y : dd == 2 ? x0.z : x0.w;
            float v1 = dd == 0 ? x1.x : dd == 1 ? x1.y : dd == 2 ? x1.z : x1.w;
            float v2 = dd == 0 ? x2.x : dd == 1 ? x2.y : dd == 2 ? x2.z : x2.w;
            float v3 = dd == 0 ? x3.x : dd == 1 ? x3.y : dd == 2 ? x3.z : x3.w;
            acc0 += v0 * wv; acc1 += v1 * wv; acc2 += v2 * wv; acc3 += v3 * wv;
        }
    }
    int lb = (b * 256 + lg * 16 + r0) * 64 + e;
    z[lb]       = silu(acc0);
    z[lb + 64]  = silu(acc1);
    z[lb + 128] = silu(acc2);
    z[lb + 192] = silu(acc3);
}

// ---------------- K2a: rearrange + depthwise 3x3 conv + silu (smem tiled) ---
// grid (B*4): block per (b,c). 256 threads.
__global__ void __launch_bounds__(256) k_dwconv(const float* __restrict__ xin,
                                                const float* __restrict__ cw,
                                                const float* __restrict__ cb,
                                                float* __restrict__ xc) {
    __shared__ float ts[66][68];   // halo
    int bc_ = blockIdx.x;
    int c = bc_ & 3, b = bc_ >> 2;
    int t = threadIdx.x;
    for (int i = t; i < 66 * 68; i += 256) ((float*)ts)[i] = 0.f;
    __syncthreads();
    const float* xb = xin + b * 16 * 16 * 64 + c * 16;
#pragma unroll
    for (int it = 0; it < 16; it++) {
        int e = it * 256 + t;
        int pq = e >> 4, ij = e & 15;
        int p = pq >> 4, q = pq & 15;
        int i2 = ij >> 2, j2 = ij & 3;
        float v = xb[pq * 64 + ij];
        ts[1 + p * 4 + i2][1 + q * 4 + j2] = v;
    }
    __syncthreads();
    float wr[9];
#pragma unroll
    for (int i = 0; i < 9; i++) wr[i] = __ldg(&cw[c * 9 + i]);
    float cbv = __ldg(&cb[c]);
    int h = t >> 2, wq = t & 3;
    float* op = xc + (bc_ * 64 + h) * 64 + wq * 16;
#pragma unroll
    for (int j = 0; j < 16; j++) {
        int wcol = wq * 16 + j;
        float acc = cbv;
#pragma unroll
        for (int di = 0; di < 3; di++)
#pragma unroll
            for (int dj = 0; dj < 3; dj++)
                acc += ts[h + di][wcol + dj] * wr[di * 3 + dj];
        op[j] = silu(acc);
    }
}

// ---------------- K2b: patch conv + BN --------------------------------------
__global__ void k_patch(const float* __restrict__ xc,
                        const float* __restrict__ pw,
                        const float* __restrict__ pb,
                        const float* __restrict__ gam,
                        const float* __restrict__ bet,
                        const float* __restrict__ mn,
                        const float* __restrict__ vr,
                        float* __restrict__ xt) {
    __shared__ __align__(16) float ws[64 * 65];
    __shared__ __align__(16) float px[16][64];
    int b = blockIdx.y, lg = blockIdx.x;
    int e = threadIdx.x, li = threadIdx.y;
    int t = li * 64 + e;
    for (int i = t; i < 4096; i += 256) ws[(i & 63) * 65 + (i >> 6)] = pw[i];
    for (int i = t; i < 1024; i += 256) {
        int row = i >> 6, m = i & 63;
        int l = lg * 16 + row;
        int ph = l >> 4, pwd = l & 15;
        int c = m >> 4, ij = m & 15, i2 = ij >> 2, j2 = ij & 3;
        px[row][m] = xc[((b * 4 + c) * 64 + ph * 4 + i2) * 64 + pwd * 4 + j2];
    }
    __syncthreads();
    float acc0 = 0.f, acc1 = 0.f, acc2 = 0.f, acc3 = 0.f;
    int r0 = li * 4;
#pragma unroll
    for (int m4 = 0; m4 < 16; m4++) {
        float4 x0 = ((const float4*)px[r0 + 0])[m4];
        float4 x1 = ((const float4*)px[r0 + 1])[m4];
        float4 x2 = ((const float4*)px[r0 + 2])[m4];
        float4 x3 = ((const float4*)px[r0 + 3])[m4];
#pragma unroll
        for (int dd = 0; dd < 4; dd++) {
            float wv = ws[(m4 * 4 + dd) * 65 + e];
            float v0 = dd == 0 ? x0.x : dd == 1 ? x0.y : dd == 2 ? x0.z : x0.w;
            float v1 = dd == 0 ? x1.x : dd == 1 ? x1.y : dd == 2 ? x1.z : x1.w;
            float v2 = dd == 0 ? x2.x : dd == 1 ? x2.y : dd == 2 ? x2.z : x2.w;
            float v3 = dd == 0 ? x3.x : dd == 1 ? x3.y : dd == 2 ? x3.z : x3.w;
            acc0 += v0 * wv; acc1 += v1 * wv; acc2 += v2 * wv; acc3 += v3 * wv;
        }
    }
    float sc = __ldg(&gam[e]) * rsqrtf(__ldg(&vr[e]) + 1e-5f);
    float pbv = __ldg(&pb[e]), mnv = __ldg(&mn[e]), btv = __ldg(&bet[e]);
    int lb = (b * 256 + lg * 16 + r0) * 64 + e;
    xt[lb]       = (acc0 + pbv - mnv) * sc + btv;
    xt[lb + 64]  = (acc1 + pbv - mnv) * sc + btv;
    xt[lb + 128] = (acc2 + pbv - mnv) * sc + btv;
    xt[lb + 192] = (acc3 + pbv - mnv) * sc + btv;
}

// ---------------- K3: register-tiled f32x2 GEMM: x_dbl + dt projections -----
// grid (4, B): block per (k,b). 256 threads = 8 warps.
// Warp w owns c-rows [w*9, w*9+9) (GEMM1) and d-rows [w*8, w*8+8) (GEMM2).
// Lane owns 4 l-pairs: l = p*64 + lane*2.
#define PCH 8
__global__ void __launch_bounds__(256, 2) k_proj(const float* __restrict__ xt,
                                                 const float* __restrict__ xpw,
                                                 const float* __restrict__ dtw,
                                                 float* __restrict__ dts,
                                                 float* __restrict__ bc) {
    __shared__ __align__(16) float ubuf[3072];      // Xs [8][256] | dws2 [24][64] f2
    __shared__ __align__(16) float2 Ws2[PCH * 72];  // duplicated weights
    __shared__ __align__(16) float dtr[24 * 256];
    int k = blockIdx.x, b = blockIdx.y;
    int t = threadIdx.x, w = t >> 5, lane = t & 31;
    int lane2 = lane * 2;
    const float* wk = xpw + k * CPROJ * 64;
    const float* xbase = xt + (b * 256 + map_l(k, t)) * 64;

    u64 acc[9][4];
#pragma unroll
    for (int ci = 0; ci < 9; ci++)
#pragma unroll
        for (int p = 0; p < 4; p++) acc[ci][p] = 0ull;

    for (int dc = 0; dc < 64; dc += PCH) {
        __syncthreads();
        {   // stage X chunk transposed: Xs[dd][l]
            float4 v0 = __ldg((const float4*)(xbase + dc));
            float4 v1 = __ldg((const float4*)(xbase + dc + 4));
            ubuf[0 * 256 + t] = v0.x; ubuf[1 * 256 + t] = v0.y;
            ubuf[2 * 256 + t] = v0.z; ubuf[3 * 256 + t] = v0.w;
            ubuf[4 * 256 + t] = v1.x; ubuf[5 * 256 + t] = v1.y;
            ubuf[6 * 256 + t] = v1.z; ubuf[7 * 256 + t] = v1.w;
        }
        for (int i = t; i < PCH * CPROJ; i += 256) {
            int dd = i & (PCH - 1), c = i / PCH;
            float wv = wk[c * 64 + dc + dd];
            Ws2[dd * 72 + c] = make_float2(wv, wv);
        }
        __syncthreads();
#pragma unroll
        for (int dd = 0; dd < PCH; dd++) {
            u64 x2[4];
#pragma unroll
            for (int p = 0; p < 4; p++)
                x2[p] = *(const u64*)&ubuf[dd * 256 + p * 64 + lane2];
#pragma unroll
            for (int ci = 0; ci < 9; ci++) {
                u64 wv = *(const u64*)&Ws2[dd * 72 + w * 9 + ci];
#pragma unroll
                for (int p = 0; p < 4; p++) acc[ci][p] = fma2(wv, x2[p], acc[ci][p]);
            }
        }
    }
    // scatter GEMM1 outputs: c<24 -> dtr smem, else -> bc global
    float* bco = bc + (b * 4 + k) * 48 * 256;
#pragma unroll
    for (int ci = 0; ci < 9; ci++) {
        int c = w * 9 + ci;
#pragma unroll
        for (int p = 0; p < 4; p++) {
            float lo, hi; unpk2(lo, hi, acc[ci][p]);
            if (c < 24) {
                dtr[c * 256 + p * 64 + lane2]     = lo;
                dtr[c * 256 + p * 64 + lane2 + 1] = hi;
            } else {
                *(float2*)&bco[(c - 24) * 256 + p * 64 + lane2] = make_float2(lo, hi);
            }
        }
    }
    __syncthreads();
    // stage dt_projs_weight duplicated: dws2[r][dout]
    float2* dws2 = (float2*)ubuf;
    const float* dwk = dtw + k * 64 * NST;
    for (int i = t; i < NST * 64; i += 256) {
        int dout = i & 63, r = i >> 6;
        float wv = dwk[dout * NST + r];
        dws2[r * 64 + dout] = make_float2(wv, wv);
    }
    __syncthreads();
    u64 acc2[8][4];
#pragma unroll
    for (int ci = 0; ci < 8; ci++)
#pragma unroll
        for (int p = 0; p < 4; p++) acc2[ci][p] = 0ull;
#pragma unroll 6
    for (int r = 0; r < NST; r++) {
        u64 x2[4];
#pragma unroll
        for (int p = 0; p < 4; p++)
            x2[p] = *(const u64*)&dtr[r * 256 + p * 64 + lane2];
#pragma unroll
        for (int ci = 0; ci < 8; ci++) {
            u64 wv = *(const u64*)&dws2[r * 64 + w * 8 + ci];
#pragma unroll
            for (int p = 0; p < 4; p++) acc2[ci][p] = fma2(wv, x2[p], acc2[ci][p]);
        }
    }
    float* dto = dts + (b * 4 + k) * 64 * 256;
#pragma unroll
    for (int ci = 0; ci < 8; ci++) {
        int dout = w * 8 + ci;
#pragma unroll
        for (int p = 0; p < 4; p++) {
            float lo, hi; unpk2(lo, hi, acc2[ci][p]);
            *(float2*)&dto[dout * 256 + p * 64 + lane2] = make_float2(lo, hi);
        }
    }
}

// ---------------- K4: selective scan (f32x2, power-tree, staged u) ----------
// grid (4, B), block 64 (thread per d).
__global__ void __launch_bounds__(64) k_scan(const float* __restrict__ xt,
                                             const float* __restrict__ dts,
                                             const float* __restrict__ bc,
                                             const float* __restrict__ alog,
                                             const float* __restrict__ dbias,
                                             const float* __restrict__ Dsv,
                                             float* __restrict__ yg) {
    __shared__ __align__(16) float sdt[64][17];
    __shared__ __align__(8) float sbc[16][48];
    __shared__ float su[16][64];
    int k = blockIdx.x, b = blockIdx.y;
    int d = threadIdx.x;
    int kd = k * 64 + d;

    float a[NST];
#pragma unroll
    for (int n = 0; n < NST; n++) a[n] = -__expf(__ldg(&alog[kd * NST + n]));
    float a0 = a[0];
    bool chain = (a0 != 0.f);
#pragma unroll
    for (int n = 1; n < NST; n++)
        chain = chain && (fabsf(a[n] - (float)(n + 1) * a0) <= 1e-4f * fabsf(a[n]));

    float bias = __ldg(&dbias[kd]);
    float Dv = __ldg(&Dsv[kd]);
    int kb = b * 4 + k;
    const float* dtp = dts + kb * 64 * 256;
    const float* bcp = bc + kb * 48 * 256;
    const float* xrow = xt + b * 256 * 64;
    float* yp = yg + kb * 256 * 64;

    u64 h2[12];
    float hs[NST];
#pragma unroll
    for (int p = 0; p < 12; p++) h2[p] = 0ull;
#pragma unroll
    for (int n = 0; n < NST; n++) hs[n] = 0.f;

    for (int l0 = 0; l0 < 256; l0 += 16) {
        __syncthreads();
        {
            const float4* src = (const float4*)(dtp + d * 256 + l0);
            float4 v0 = src[0], v1 = src[1], v2 = src[2], v3 = src[3];
            sdt[d][0] = v0.x; sdt[d][1] = v0.y; sdt[d][2] = v0.z; sdt[d][3] = v0.w;
            sdt[d][4] = v1.x; sdt[d][5] = v1.y; sdt[d][6] = v1.z; sdt[d][7] = v1.w;
            sdt[d][8] = v2.x; sdt[d][9] = v2.y; sdt[d][10] = v2.z; sdt[d][11] = v2.w;
            sdt[d][12] = v3.x; sdt[d][13] = v3.y; sdt[d][14] = v3.z; sdt[d][15] = v3.w;
        }
#pragma unroll
        for (int m = 0; m < 12; m++) {
            int idx = d * 12 + m;
            int j = idx >> 4, i = idx & 15;
            sbc[i][j] = bcp[j * 256 + l0 + i];
        }
#pragma unroll
        for (int i = 0; i < 16; i++)
            su[i][d] = __ldg(&xrow[map_l(k, l0 + i) * 64 + d]);
        __syncthreads();
        if (chain) {
#pragma unroll 2
            for (int i = 0; i < 16; i++) {
                int l = l0 + i;
                float xv = sdt[d][i] + bias;
                float ex = __expf(xv);
                float delta = (xv > 15.f) ? xv : __logf(1.f + ex);
                float u = su[i][d];
                float du = delta * u;
                float q = __expf(delta * a0);
                float q2s = q * q, q4s = q2s * q2s, q8s = q4s * q4s, q16s = q8s * q8s;
                u64 Q2 = pk2(q2s, q2s), Q4 = pk2(q4s, q4s);
                u64 Q8 = pk2(q8s, q8s), Q16 = pk2(q16s, q16s);
                u64 P[12];
                P[0] = pk2(q, q2s);
                P[1] = mul2(P[0], Q2);
                P[2] = mul2(P[0], Q4);  P[3] = mul2(P[1], Q4);
                P[4] = mul2(P[0], Q8);  P[5] = mul2(P[1], Q8);
                P[6] = mul2(P[2], Q8);  P[7] = mul2(P[3], Q8);
                P[8] = mul2(P[0], Q16); P[9] = mul2(P[1], Q16);
                P[10] = mul2(P[2], Q16); P[11] = mul2(P[3], Q16);
                u64 du2 = pk2(du, du);
                u64 y2 = 0ull;
#pragma unroll
                for (int p = 0; p < 12; p++) {
                    u64 B2 = *(const u64*)&sbc[i][2 * p];
                    u64 C2 = *(const u64*)&sbc[i][24 + 2 * p];
                    h2[p] = fma2(P[p], h2[p], mul2(du2, B2));
                    y2 = fma2(h2[p], C2, y2);
                }
                float ylo, yhi;
                unpk2(ylo, yhi, y2);
                yp[l * 64 + d] = ylo + yhi + Dv * u;
            }
        } else {
#pragma unroll 1
            for (int i = 0; i < 16; i++) {
                int l = l0 + i;
                float xv = sdt[d][i] + bias;
                float ex = __expf(xv);
                float delta = (xv > 15.f) ? xv : __logf(1.f + ex);
                float u = su[i][d];
                float du = delta * u;
                float y = 0.f;
#pragma unroll
                for (int n = 0; n < NST; n++) {
                    float dAv = __expf(delta * a[n]);
                    hs[n] = dAv * hs[n] + du * sbc[i][n];
                    y += hs[n] * sbc[i][24 + n];
                }
                yp[l * 64 + d] = y + Dv * u;
            }
        }
    }
}

// ---------------- K5: combine + LN + gate + out_proj ------------------------
__global__ void __launch_bounds__(256) k_final(const float* __restrict__ yg,
                                               const float* __restrict__ zg,
                                               const float* __restrict__ lng,
                                               const float* __restrict__ lnb,
                                               const float* __restrict__ wo,
                                               float* __restrict__ out) {
    __shared__ __align__(16) float ws[64 * 68];   // ws[e*68+d], padded
    __shared__ float gs[64], bs[64];
    int b = blockIdx.x, l = threadIdx.x;
    for (int i = l; i < 4096; i += 256) {
        int dd = i >> 6, ee = i & 63;
        ws[ee * 68 + dd] = wo[i];
    }
    if (l < 64) { gs[l] = lng[l]; bs[l] = lnb[l]; }
    __syncthreads();
    int l1 = ((l & 15) << 4) | (l >> 4);
    int b4 = b * 4;
    const float4* y0 = (const float4*)(yg + ((b4 + 0) * 256 + l) * 64);
    const float4* y1 = (const float4*)(yg + ((b4 + 1) * 256 + l1) * 64);
    const float4* y2 = (const float4*)(yg + ((b4 + 2) * 256 + (255 - l)) * 64);
    const float4* y3 = (const float4*)(yg + ((b4 + 3) * 256 + (255 - l1)) * 64);
    float yv[64];
    float mu = 0.f;
#pragma unroll
    for (int i = 0; i < 16; i++) {
        float4 v0 = y0[i], v1 = y1[i], v2 = y2[i], v3 = y3[i];
        yv[4 * i + 0] = v0.x + v1.x + v2.x + v3.x;
        yv[4 * i + 1] = v0.y + v1.y + v2.y + v3.y;
        yv[4 * i + 2] = v0.z + v1.z + v2.z + v3.z;
        yv[4 * i + 3] = v0.w + v1.w + v2.w + v3.w;
        mu += yv[4 * i] + yv[4 * i + 1] + yv[4 * i + 2] + yv[4 * i + 3];
    }
    mu *= (1.f / 64.f);
    float var = 0.f;
#pragma unroll
    for (int e = 0; e < 64; e++) {
        float tv = yv[e] - mu;
        var += tv * tv;
    }
    var *= (1.f / 64.f);
    float rs = rsqrtf(var + 1e-5f);
    const float4* zp = (const float4*)(zg + (b * 256 + l) * 64);
#pragma unroll
    for (int i = 0; i < 16; i++) {
        float4 zv = zp[i];
        yv[4 * i + 0] = ((yv[4 * i + 0] - mu) * rs * gs[4 * i + 0] + bs[4 * i + 0]) * zv.x;
        yv[4 * i + 1] = ((yv[4 * i + 1] - mu) * rs * gs[4 * i + 1] + bs[4 * i + 1]) * zv.y;
        yv[4 * i + 2] = ((yv[4 * i + 2] - mu) * rs * gs[4 * i + 2] + bs[4 * i + 2]) * zv.z;
        yv[4 * i + 3] = ((yv[4 * i + 3] - mu) * rs * gs[4 * i + 3] + bs[4 * i + 3]) * zv.w;
    }
    float4* op = (float4*)(out + (b * 256 + l) * 64);
#pragma unroll 1
    for (int dc = 0; dc < 16; dc++) {
        float4 acc = {0.f, 0.f, 0.f, 0.f};
#pragma unroll
        for (int e = 0; e < 64; e++) {
            float4 w4 = *(const float4*)&ws[e * 68 + dc * 4];
            acc.x += yv[e] * w4.x;
            acc.y += yv[e] * w4.y;
            acc.z += yv[e] * w4.z;
            acc.w += yv[e] * w4.w;
        }
        op[dc] = acc;
    }
}

// ---------------- launch -----------------------------------------------------
extern "C" void kernel_launch(void* const* d_in, const int* in_sizes, int n_in,
                              void* d_out, int out_size) {
    const float* x_in   = (const float*)d_in[0];
    const float* ipw    = (const float*)d_in[1];
    const float* conv_w = (const float*)d_in[2];
    const float* conv_b = (const float*)d_in[3];
    const float* patch_w= (const float*)d_in[4];
    const float* patch_b= (const float*)d_in[5];
    const float* bn_g   = (const float*)d_in[6];
    const float* bn_b   = (const float*)d_in[7];
    const float* bn_m   = (const float*)d_in[8];
    const float* bn_v   = (const float*)d_in[9];
    const float* xpw    = (const float*)d_in[10];
    const float* dtw    = (const float*)d_in[11];
    const float* dtb    = (const float*)d_in[12];
    const float* alog   = (const float*)d_in[13];
    const float* Dsv    = (const float*)d_in[14];
    const float* lng    = (const float*)d_in[15];
    const float* lnb    = (const float*)d_in[16];
    const float* wo     = (const float*)d_in[17];
    float* out = (float*)d_out;

    float *zg, *xc, *xt, *dts, *bcv, *yg;
    cudaGetSymbolAddress((void**)&zg,  g_z);
    cudaGetSymbolAddress((void**)&xc,  g_xconv);
    cudaGetSymbolAddress((void**)&xt,  g_xt);
    cudaGetSymbolAddress((void**)&dts, g_dts);
    cudaGetSymbolAddress((void**)&bcv, g_bc);
    cudaGetSymbolAddress((void**)&yg,  g_y);

    dim3 blk64_4(64, 4);
    k_zproj<<<dim3(16, BATCH), blk64_4>>>(x_in, ipw, zg);
    k_dwconv<<<BATCH * 4, 256>>>(x_in, conv_w, conv_b, xc);
    k_patch<<<dim3(16, BATCH), blk64_4>>>(xc, patch_w, patch_b,
                                          bn_g, bn_b, bn_m, bn_v, xt);
    k_proj<<<dim3(4, BATCH), 256>>>(xt, xpw, dtw, dts, bcv);
    k_scan<<<dim3(4, BATCH), 64>>>(xt, dts, bcv, alog, dtb, Dsv, yg);
    k_final<<<BATCH, 256>>>(yg, zg, lng, lnb, wo, out);
}

// round 4
// speedup vs baseline: 3.4314x; 1.1143x over previous
#include <cuda_runtime.h>
#include <cuda_bf16.h>

#define BATCH 256
#define L 256
#define D 64
#define NST 24
#define CPROJ 72   // DT_RANK + 2*NST

typedef unsigned long long u64;

// ---------------- scratch ----------------------------------------------------
__device__ float g_z[BATCH * L * D];            // (b,l,e)
__device__ float g_xconv[BATCH * 4 * 64 * 64];  // (b,c,h,w)
__device__ float g_xt[BATCH * L * D];           // (b,l,d)
__device__ float g_dtr[BATCH * 4 * NST * L];    // (b,k,r,l)  low-rank dt
__device__ float g_bc[BATCH * 4 * 48 * L];      // (b,k,j,l)  j:0..23=B, 24..47=C
__device__ float g_y[BATCH * 4 * L * D];        // (b,k,slot,d)  slot=map_l(k,l)

__device__ __forceinline__ int map_l(int k, int l) {
    int lm = (k & 2) ? (255 - l) : l;
    if (k & 1) lm = ((lm & 15) << 4) | (lm >> 4);
    return lm;
}
__device__ __forceinline__ float silu(float x) { return x / (1.f + __expf(-x)); }

__device__ __forceinline__ u64 pk2(float lo, float hi) {
    u64 r; asm("mov.b64 %0,{%1,%2};" : "=l"(r) : "f"(lo), "f"(hi)); return r;
}
__device__ __forceinline__ void unpk2(float& lo, float& hi, u64 v) {
    asm("mov.b64 {%0,%1},%2;" : "=f"(lo), "=f"(hi) : "l"(v));
}
__device__ __forceinline__ u64 mul2(u64 a, u64 b) {
    u64 r; asm("mul.rn.f32x2 %0,%1,%2;" : "=l"(r) : "l"(a), "l"(b)); return r;
}
__device__ __forceinline__ u64 fma2(u64 a, u64 b, u64 c) {
    u64 r; asm("fma.rn.f32x2 %0,%1,%2,%3;" : "=l"(r) : "l"(a), "l"(b), "l"(c)); return r;
}

// ---------------- K1: z = silu(x_in @ in_proj_w^T), 64 rows per block -------
__global__ void __launch_bounds__(512) k_zproj(const float* __restrict__ xin,
                                               const float* __restrict__ w,
                                               float* __restrict__ z) {
    __shared__ __align__(16) float ws[64 * 65];
    __shared__ __align__(16) float xs[64][64];
    int b = blockIdx.y, lg = blockIdx.x;          // lg: 0..3
    int e = threadIdx.x, li = threadIdx.y;        // 64 x 8
    int t = li * 64 + e;
    for (int i = t; i < 4096; i += 512) ws[(i & 63) * 65 + (i >> 6)] = w[i];
    for (int i = t; i < 1024; i += 512) {
        int row = i >> 4, m = i & 15;
        ((float4*)xs[row])[m] =
            ((const float4*)(xin + (b * 256 + lg * 64 + row) * 64))[m];
    }
    __syncthreads();
    float acc[8];
#pragma unroll
    for (int j = 0; j < 8; j++) acc[j] = 0.f;
    int r0 = li * 8;
#pragma unroll
    for (int d4 = 0; d4 < 16; d4++) {
        float4 xv[8];
#pragma unroll
        for (int j = 0; j < 8; j++) xv[j] = ((const float4*)xs[r0 + j])[d4];
#pragma unroll
        for (int dd = 0; dd < 4; dd++) {
            float wv = ws[(d4 * 4 + dd) * 65 + e];
#pragma unroll
            for (int j = 0; j < 8; j++) {
                float v = dd == 0 ? xv[j].x : dd == 1 ? xv[j].y : dd == 2 ? xv[j].z : xv[j].w;
                acc[j] += v * wv;
            }
        }
    }
#pragma unroll
    for (int j = 0; j < 8; j++)
        z[(b * 256 + lg * 64 + r0 + j) * 64 + e] = silu(acc[j]);
}

// ---------------- K2a: rearrange + depthwise 3x3 conv + silu ----------------
__global__ void __launch_bounds__(256) k_dwconv(const float* __restrict__ xin,
                                                const float* __restrict__ cw,
                                                const float* __restrict__ cb,
                                                float* __restrict__ xc) {
    __shared__ float ts[66][68];
    int bc_ = blockIdx.x;
    int c = bc_ & 3, b = bc_ >> 2;
    int t = threadIdx.x;
    for (int i = t; i < 66 * 68; i += 256) ((float*)ts)[i] = 0.f;
    __syncthreads();
    const float* xb = xin + b * 16 * 16 * 64 + c * 16;
#pragma unroll
    for (int it = 0; it < 16; it++) {
        int e = it * 256 + t;
        int pq = e >> 4, ij = e & 15;
        int p = pq >> 4, q = pq & 15;
        int i2 = ij >> 2, j2 = ij & 3;
        ts[1 + p * 4 + i2][1 + q * 4 + j2] = xb[pq * 64 + ij];
    }
    __syncthreads();
    float wr[9];
#pragma unroll
    for (int i = 0; i < 9; i++) wr[i] = __ldg(&cw[c * 9 + i]);
    float cbv = __ldg(&cb[c]);
    int h = t >> 2, wq = t & 3;
    float* op = xc + (bc_ * 64 + h) * 64 + wq * 16;
#pragma unroll
    for (int j = 0; j < 16; j++) {
        int wcol = wq * 16 + j;
        float acc = cbv;
#pragma unroll
        for (int di = 0; di < 3; di++)
#pragma unroll
            for (int dj = 0; dj < 3; dj++)
                acc += ts[h + di][wcol + dj] * wr[di * 3 + dj];
        op[j] = silu(acc);
    }
}

// ---------------- K2b: patch conv + BN, 64 rows per block -------------------
__global__ void __launch_bounds__(512) k_patch(const float* __restrict__ xc,
                                               const float* __restrict__ pw,
                                               const float* __restrict__ pb,
                                               const float* __restrict__ gam,
                                               const float* __restrict__ bet,
                                               const float* __restrict__ mn,
                                               const float* __restrict__ vr,
                                               float* __restrict__ xt) {
    __shared__ __align__(16) float ws[64 * 65];
    __shared__ __align__(16) float px[64][64];
    int b = blockIdx.y, lg = blockIdx.x;
    int e = threadIdx.x, li = threadIdx.y;
    int t = li * 64 + e;
    for (int i = t; i < 4096; i += 512) ws[(i & 63) * 65 + (i >> 6)] = pw[i];
    for (int i = t; i < 4096; i += 512) {
        int row = i >> 6, m = i & 63;
        int l = lg * 64 + row;
        int ph = l >> 4, pwd = l & 15;
        int c = m >> 4, ij = m & 15, i2 = ij >> 2, j2 = ij & 3;
        px[row][m] = xc[((b * 4 + c) * 64 + ph * 4 + i2) * 64 + pwd * 4 + j2];
    }
    __syncthreads();
    float acc[8];
#pragma unroll
    for (int j = 0; j < 8; j++) acc[j] = 0.f;
    int r0 = li * 8;
#pragma unroll
    for (int m4 = 0; m4 < 16; m4++) {
        float4 xv[8];
#pragma unroll
        for (int j = 0; j < 8; j++) xv[j] = ((const float4*)px[r0 + j])[m4];
#pragma unroll
        for (int dd = 0; dd < 4; dd++) {
            float wv = ws[(m4 * 4 + dd) * 65 + e];
#pragma unroll
            for (int j = 0; j < 8; j++) {
                float v = dd == 0 ? xv[j].x : dd == 1 ? xv[j].y : dd == 2 ? xv[j].z : xv[j].w;
                acc[j] += v * wv;
            }
        }
    }
    float sc = __ldg(&gam[e]) * rsqrtf(__ldg(&vr[e]) + 1e-5f);
    float pbv = __ldg(&pb[e]), mnv = __ldg(&mn[e]), btv = __ldg(&bet[e]);
#pragma unroll
    for (int j = 0; j < 8; j++)
        xt[(b * 256 + lg * 64 + r0 + j) * 64 + e] = (acc[j] + pbv - mnv) * sc + btv;
}

// ---------------- K3: x_dbl projection only (72x64 GEMM, f32x2) -------------
// grid (4, B), 256 threads = 8 warps. Warp owns 9 c-rows, lane owns 4 l-pairs.
#define PCH 8
__global__ void __launch_bounds__(256, 2) k_proj(const float* __restrict__ xt,
                                                 const float* __restrict__ xpw,
                                                 float* __restrict__ dtrg,
                                                 float* __restrict__ bc) {
    __shared__ __align__(16) float ubuf[PCH * 256];   // X chunk transposed
    __shared__ __align__(16) float2 Ws2[PCH * 72];
    int k = blockIdx.x, b = blockIdx.y;
    int t = threadIdx.x, w = t >> 5, lane = t & 31;
    int lane2 = lane * 2;
    const float* wk = xpw + k * CPROJ * 64;
    const float* xbase = xt + (b * 256 + map_l(k, t)) * 64;

    u64 acc[9][4];
#pragma unroll
    for (int ci = 0; ci < 9; ci++)
#pragma unroll
        for (int p = 0; p < 4; p++) acc[ci][p] = 0ull;

    for (int dc = 0; dc < 64; dc += PCH) {
        __syncthreads();
        {
            float4 v0 = __ldg((const float4*)(xbase + dc));
            float4 v1 = __ldg((const float4*)(xbase + dc + 4));
            ubuf[0 * 256 + t] = v0.x; ubuf[1 * 256 + t] = v0.y;
            ubuf[2 * 256 + t] = v0.z; ubuf[3 * 256 + t] = v0.w;
            ubuf[4 * 256 + t] = v1.x; ubuf[5 * 256 + t] = v1.y;
            ubuf[6 * 256 + t] = v1.z; ubuf[7 * 256 + t] = v1.w;
        }
        for (int i = t; i < PCH * CPROJ; i += 256) {
            int dd = i & (PCH - 1), c = i / PCH;
            float wv = wk[c * 64 + dc + dd];
            Ws2[dd * 72 + c] = make_float2(wv, wv);
        }
        __syncthreads();
#pragma unroll
        for (int dd = 0; dd < PCH; dd++) {
            u64 x2[4];
#pragma unroll
            for (int p = 0; p < 4; p++)
                x2[p] = *(const u64*)&ubuf[dd * 256 + p * 64 + lane2];
#pragma unroll
            for (int ci = 0; ci < 9; ci++) {
                u64 wv = *(const u64*)&Ws2[dd * 72 + w * 9 + ci];
#pragma unroll
                for (int p = 0; p < 4; p++) acc[ci][p] = fma2(wv, x2[p], acc[ci][p]);
            }
        }
    }
    float* dto = dtrg + (b * 4 + k) * NST * 256;
    float* bco = bc + (b * 4 + k) * 48 * 256;
#pragma unroll
    for (int ci = 0; ci < 9; ci++) {
        int c = w * 9 + ci;
#pragma unroll
        for (int p = 0; p < 4; p++) {
            float lo, hi; unpk2(lo, hi, acc[ci][p]);
            if (c < NST)
                *(float2*)&dto[c * 256 + p * 64 + lane2] = make_float2(lo, hi);
            else
                *(float2*)&bco[(c - NST) * 256 + p * 64 + lane2] = make_float2(lo, hi);
        }
    }
}

// ---------------- K4: scan with fused dt projection --------------------------
// grid (4, B), block 64 (thread per d). Writes y to combined slot map_l(k,l).
__global__ void __launch_bounds__(64) k_scan(const float* __restrict__ xt,
                                             const float* __restrict__ dtrg,
                                             const float* __restrict__ bc,
                                             const float* __restrict__ dtw_g,
                                             const float* __restrict__ alog,
                                             const float* __restrict__ dbias,
                                             const float* __restrict__ Dsv,
                                             float* __restrict__ yg) {
    __shared__ __align__(8) float sbc[16][48];
    __shared__ __align__(8) float sdtr[NST * 16];
    __shared__ float su[16][64];
    int k = blockIdx.x, b = blockIdx.y;
    int d = threadIdx.x;
    int kd = k * 64 + d;

    float dtw[NST];
    {
        const float4* dwp = (const float4*)(dtw_g + kd * NST);
#pragma unroll
        for (int i = 0; i < 6; i++) {
            float4 v = __ldg(dwp + i);
            dtw[4 * i] = v.x; dtw[4 * i + 1] = v.y;
            dtw[4 * i + 2] = v.z; dtw[4 * i + 3] = v.w;
        }
    }
    float a0 = -__expf(__ldg(&alog[kd * NST]));
    bool chain = (a0 != 0.f);
#pragma unroll
    for (int n = 1; n < NST; n++) {
        float an = -__expf(__ldg(&alog[kd * NST + n]));
        chain = chain && (fabsf(an - (float)(n + 1) * a0) <= 1e-4f * fabsf(an));
    }
    float bias = __ldg(&dbias[kd]);
    float Dv = __ldg(&Dsv[kd]);
    int kb = b * 4 + k;
    const float* dtrp = dtrg + kb * NST * 256;
    const float* bcp = bc + kb * 48 * 256;
    const float* xrow = xt + b * 256 * 64;
    float* yp = yg + kb * 256 * 64;

    u64 h2[12];
#pragma unroll
    for (int p = 0; p < 12; p++) h2[p] = 0ull;

    for (int l0 = 0; l0 < 256; l0 += 16) {
        __syncthreads();
#pragma unroll
        for (int m = 0; m < 12; m++) {
            int idx = d * 12 + m;
            sbc[idx & 15][idx >> 4] = bcp[(idx >> 4) * 256 + l0 + (idx & 15)];
        }
#pragma unroll
        for (int m = 0; m < 6; m++) {
            int idx = d * 6 + m;
            sdtr[idx] = dtrp[(idx >> 4) * 256 + l0 + (idx & 15)];
        }
#pragma unroll
        for (int i = 0; i < 16; i++)
            su[i][d] = __ldg(&xrow[map_l(k, l0 + i) * 64 + d]);
        __syncthreads();

        // dt for the chunk: dt[l] = sum_r dtr[r][l] * dtw[r], packed over l-pairs
        float dtc[16];
        {
            u64 dt2[8];
#pragma unroll
            for (int ip = 0; ip < 8; ip++) dt2[ip] = 0ull;
#pragma unroll
            for (int r = 0; r < NST; r++) {
                u64 wp = pk2(dtw[r], dtw[r]);
#pragma unroll
                for (int ip = 0; ip < 8; ip++)
                    dt2[ip] = fma2(wp, *(const u64*)&sdtr[r * 16 + 2 * ip], dt2[ip]);
            }
#pragma unroll
            for (int ip = 0; ip < 8; ip++) unpk2(dtc[2 * ip], dtc[2 * ip + 1], dt2[ip]);
        }

        if (chain) {
#pragma unroll 2
            for (int i = 0; i < 16; i++) {
                int l = l0 + i;
                float xv = dtc[i] + bias;
                float delta = (xv > 15.f) ? xv : __logf(1.f + __expf(xv));
                float u = su[i][d];
                float du = delta * u;
                float q = __expf(delta * a0);
                float q2s = q * q, q4s = q2s * q2s, q8s = q4s * q4s, q16s = q8s * q8s;
                u64 Q2 = pk2(q2s, q2s), Q4 = pk2(q4s, q4s);
                u64 Q8 = pk2(q8s, q8s), Q16 = pk2(q16s, q16s);
                u64 P[12];
                P[0] = pk2(q, q2s);
                P[1] = mul2(P[0], Q2);
                P[2] = mul2(P[0], Q4);  P[3] = mul2(P[1], Q4);
                P[4] = mul2(P[0], Q8);  P[5] = mul2(P[1], Q8);
                P[6] = mul2(P[2], Q8);  P[7] = mul2(P[3], Q8);
                P[8] = mul2(P[0], Q16); P[9] = mul2(P[1], Q16);
                P[10] = mul2(P[2], Q16); P[11] = mul2(P[3], Q16);
                u64 du2 = pk2(du, du);
                u64 y2 = 0ull;
#pragma unroll
                for (int p = 0; p < 12; p++) {
                    u64 B2 = *(const u64*)&sbc[i][2 * p];
                    u64 C2 = *(const u64*)&sbc[i][24 + 2 * p];
                    h2[p] = fma2(P[p], h2[p], mul2(du2, B2));
                    y2 = fma2(h2[p], C2, y2);
                }
                float ylo, yhi;
                unpk2(ylo, yhi, y2);
                yp[map_l(k, l) * 64 + d] = ylo + yhi + Dv * u;
            }
        } else {
#pragma unroll 1
            for (int i = 0; i < 16; i++) {
                int l = l0 + i;
                float xv = dtc[i] + bias;
                float delta = (xv > 15.f) ? xv : __logf(1.f + __expf(xv));
                float u = su[i][d];
                float du = delta * u;
                u64 du2 = pk2(du, du);
                u64 y2 = 0ull;
#pragma unroll
                for (int p = 0; p < 12; p++) {
                    float alo = -__expf(__ldg(&alog[kd * NST + 2 * p]));
                    float ahi = -__expf(__ldg(&alog[kd * NST + 2 * p + 1]));
                    u64 dA = pk2(__expf(delta * alo), __expf(delta * ahi));
                    u64 B2 = *(const u64*)&sbc[i][2 * p];
                    u64 C2 = *(const u64*)&sbc[i][24 + 2 * p];
                    h2[p] = fma2(dA, h2[p], mul2(du2, B2));
                    y2 = fma2(h2[p], C2, y2);
                }
                float ylo, yhi;
                unpk2(ylo, yhi, y2);
                yp[map_l(k, l) * 64 + d] = ylo + yhi + Dv * u;
            }
        }
    }
}

// ---------------- K5: combine + LN + gate + out_proj ------------------------
// grid (2, B), block 128: thread per l (half the rows).
__global__ void __launch_bounds__(128) k_final(const float* __restrict__ yg,
                                               const float* __restrict__ zg,
                                               const float* __restrict__ lng,
                                               const float* __restrict__ lnb,
                                               const float* __restrict__ wo,
                                               float* __restrict__ out) {
    __shared__ __align__(16) float ws[64 * 68];
    __shared__ float gs[64], bs[64];
    int b = blockIdx.y, half = blockIdx.x;
    int tid = threadIdx.x;
    int l = half * 128 + tid;
    for (int i = tid; i < 4096; i += 128) {
        int dd = i >> 6, ee = i & 63;
        ws[ee * 68 + dd] = wo[i];
    }
    if (tid < 64) { gs[tid] = lng[tid]; bs[tid] = lnb[tid]; }
    __syncthreads();
    int b4 = b * 4;
    const float4* y0 = (const float4*)(yg + ((b4 + 0) * 256 + l) * 64);
    const float4* y1 = (const float4*)(yg + ((b4 + 1) * 256 + l) * 64);
    const float4* y2 = (const float4*)(yg + ((b4 + 2) * 256 + l) * 64);
    const float4* y3 = (const float4*)(yg + ((b4 + 3) * 256 + l) * 64);
    float yv[64];
    float mu = 0.f;
#pragma unroll
    for (int i = 0; i < 16; i++) {
        float4 v0 = y0[i], v1 = y1[i], v2 = y2[i], v3 = y3[i];
        yv[4 * i + 0] = v0.x + v1.x + v2.x + v3.x;
        yv[4 * i + 1] = v0.y + v1.y + v2.y + v3.y;
        yv[4 * i + 2] = v0.z + v1.z + v2.z + v3.z;
        yv[4 * i + 3] = v0.w + v1.w + v2.w + v3.w;
        mu += yv[4 * i] + yv[4 * i + 1] + yv[4 * i + 2] + yv[4 * i + 3];
    }
    mu *= (1.f / 64.f);
    float var = 0.f;
#pragma unroll
    for (int e = 0; e < 64; e++) {
        float tv = yv[e] - mu;
        var += tv * tv;
    }
    var *= (1.f / 64.f);
    float rs = rsqrtf(var + 1e-5f);
    const float4* zp = (const float4*)(zg + (b * 256 + l) * 64);
#pragma unroll
    for (int i = 0; i < 16; i++) {
        float4 zv = zp[i];
        yv[4 * i + 0] = ((yv[4 * i + 0] - mu) * rs * gs[4 * i + 0] + bs[4 * i + 0]) * zv.x;
        yv[4 * i + 1] = ((yv[4 * i + 1] - mu) * rs * gs[4 * i + 1] + bs[4 * i + 1]) * zv.y;
        yv[4 * i + 2] = ((yv[4 * i + 2] - mu) * rs * gs[4 * i + 2] + bs[4 * i + 2]) * zv.z;
        yv[4 * i + 3] = ((yv[4 * i + 3] - mu) * rs * gs[4 * i + 3] + bs[4 * i + 3]) * zv.w;
    }
    float4* op = (float4*)(out + (b * 256 + l) * 64);
#pragma unroll 1
    for (int dc = 0; dc < 16; dc++) {
        float4 acc = {0.f, 0.f, 0.f, 0.f};
#pragma unroll
        for (int e = 0; e < 64; e++) {
            float4 w4 = *(const float4*)&ws[e * 68 + dc * 4];
            acc.x += yv[e] * w4.x;
            acc.y += yv[e] * w4.y;
            acc.z += yv[e] * w4.z;
            acc.w += yv[e] * w4.w;
        }
        op[dc] = acc;
    }
}

// ---------------- launch -----------------------------------------------------
extern "C" void kernel_launch(void* const* d_in, const int* in_sizes, int n_in,
                              void* d_out, int out_size) {
    const float* x_in   = (const float*)d_in[0];
    const float* ipw    = (const float*)d_in[1];
    const float* conv_w = (const float*)d_in[2];
    const float* conv_b = (const float*)d_in[3];
    const float* patch_w= (const float*)d_in[4];
    const float* patch_b= (const float*)d_in[5];
    const float* bn_g   = (const float*)d_in[6];
    const float* bn_b   = (const float*)d_in[7];
    const float* bn_m   = (const float*)d_in[8];
    const float* bn_v   = (const float*)d_in[9];
    const float* xpw    = (const float*)d_in[10];
    const float* dtw    = (const float*)d_in[11];
    const float* dtb    = (const float*)d_in[12];
    const float* alog   = (const float*)d_in[13];
    const float* Dsv    = (const float*)d_in[14];
    const float* lng    = (const float*)d_in[15];
    const float* lnb    = (const float*)d_in[16];
    const float* wo     = (const float*)d_in[17];
    float* out = (float*)d_out;

    float *zg, *xc, *xt, *dtrg, *bcv, *yg;
    cudaGetSymbolAddress((void**)&zg,   g_z);
    cudaGetSymbolAddress((void**)&xc,   g_xconv);
    cudaGetSymbolAddress((void**)&xt,   g_xt);
    cudaGetSymbolAddress((void**)&dtrg, g_dtr);
    cudaGetSymbolAddress((void**)&bcv,  g_bc);
    cudaGetSymbolAddress((void**)&yg,   g_y);

    dim3 blk64_8(64, 8);
    k_zproj<<<dim3(4, BATCH), blk64_8>>>(x_in, ipw, zg);
    k_dwconv<<<BATCH * 4, 256>>>(x_in, conv_w, conv_b, xc);
    k_patch<<<dim3(4, BATCH), blk64_8>>>(xc, patch_w, patch_b,
                                         bn_g, bn_b, bn_m, bn_v, xt);
    k_proj<<<dim3(4, BATCH), 256>>>(xt, xpw, dtrg, bcv);
    k_scan<<<dim3(4, BATCH), 64>>>(xt, dtrg, bcv, dtw, alog, dtb, Dsv, yg);
    k_final<<<dim3(2, BATCH), 128>>>(yg, zg, lng, lnb, wo, out);
}

// round 5
// speedup vs baseline: 3.6181x; 1.0544x over previous
#include <cuda_runtime.h>
#include <cuda_bf16.h>

#define BATCH 256
#define L 256
#define D 64
#define NST 24
#define CPROJ 72   // DT_RANK + 2*NST

typedef unsigned long long u64;

// ---------------- scratch ----------------------------------------------------
__device__ float g_z[BATCH * L * D];            // (b,l,e)
__device__ float g_xconv[BATCH * 4 * 64 * 64];  // (b,c,h,w)
__device__ float g_xt[BATCH * L * D];           // (b,l,d)
__device__ float g_dtr[BATCH * 4 * NST * L];    // (b,k,r,l)
__device__ float g_bc[BATCH * 4 * 48 * L];      // (b,k,j,l)  j:0..23=B, 24..47=C
__device__ float g_y[BATCH * 4 * L * D];        // (b,k,slot,d) slot=map_l(k,l)

__device__ __forceinline__ int map_l(int k, int l) {
    int lm = (k & 2) ? (255 - l) : l;
    if (k & 1) lm = ((lm & 15) << 4) | (lm >> 4);
    return lm;
}
__device__ __forceinline__ float silu(float x) { return x / (1.f + __expf(-x)); }

__device__ __forceinline__ u64 pk2(float lo, float hi) {
    u64 r; asm("mov.b64 %0,{%1,%2};" : "=l"(r) : "f"(lo), "f"(hi)); return r;
}
__device__ __forceinline__ void unpk2(float& lo, float& hi, u64 v) {
    asm("mov.b64 {%0,%1},%2;" : "=f"(lo), "=f"(hi) : "l"(v));
}
__device__ __forceinline__ u64 mul2(u64 a, u64 b) {
    u64 r; asm("mul.rn.f32x2 %0,%1,%2;" : "=l"(r) : "l"(a), "l"(b)); return r;
}
__device__ __forceinline__ u64 fma2(u64 a, u64 b, u64 c) {
    u64 r; asm("fma.rn.f32x2 %0,%1,%2,%3;" : "=l"(r) : "l"(a), "l"(b), "l"(c)); return r;
}
__device__ __forceinline__ unsigned f2tf(float f) {
    unsigned u; asm("cvt.rna.tf32.f32 %0,%1;" : "=r"(u) : "f"(f)); return u;
}
__device__ __forceinline__ void mma_tf32(float c[4],
                                         unsigned a0, unsigned a1, unsigned a2, unsigned a3,
                                         unsigned b0, unsigned b1) {
    asm volatile(
        "mma.sync.aligned.m16n8k8.row.col.f32.tf32.tf32.f32 "
        "{%0,%1,%2,%3},{%4,%5,%6,%7},{%8,%9},{%0,%1,%2,%3};"
        : "+f"(c[0]), "+f"(c[1]), "+f"(c[2]), "+f"(c[3])
        : "r"(a0), "r"(a1), "r"(a2), "r"(a3), "r"(b0), "r"(b1));
}

// ---------------- K1: z = silu(x_in @ in_proj_w^T) --------------------------
__global__ void __launch_bounds__(512) k_zproj(const float* __restrict__ xin,
                                               const float* __restrict__ w,
                                               float* __restrict__ z) {
    __shared__ __align__(16) float ws[64 * 65];
    __shared__ __align__(16) float xs[64][64];
    int b = blockIdx.y, lg = blockIdx.x;
    int e = threadIdx.x, li = threadIdx.y;
    int t = li * 64 + e;
    for (int i = t; i < 4096; i += 512) ws[(i & 63) * 65 + (i >> 6)] = w[i];
    for (int i = t; i < 1024; i += 512) {
        int row = i >> 4, m = i & 15;
        ((float4*)xs[row])[m] =
            ((const float4*)(xin + (b * 256 + lg * 64 + row) * 64))[m];
    }
    __syncthreads();
    float acc[8];
#pragma unroll
    for (int j = 0; j < 8; j++) acc[j] = 0.f;
    int r0 = li * 8;
#pragma unroll
    for (int d4 = 0; d4 < 16; d4++) {
        float4 xv[8];
#pragma unroll
        for (int j = 0; j < 8; j++) xv[j] = ((const float4*)xs[r0 + j])[d4];
#pragma unroll
        for (int dd = 0; dd < 4; dd++) {
            float wv = ws[(d4 * 4 + dd) * 65 + e];
#pragma unroll
            for (int j = 0; j < 8; j++) {
                float v = dd == 0 ? xv[j].x : dd == 1 ? xv[j].y : dd == 2 ? xv[j].z : xv[j].w;
                acc[j] += v * wv;
            }
        }
    }
#pragma unroll
    for (int j = 0; j < 8; j++)
        z[(b * 256 + lg * 64 + r0 + j) * 64 + e] = silu(acc[j]);
}

// ---------------- K2a: depthwise conv ----------------------------------------
__global__ void __launch_bounds__(256) k_dwconv(const float* __restrict__ xin,
                                                const float* __restrict__ cw,
                                                const float* __restrict__ cb,
                                                float* __restrict__ xc) {
    __shared__ float ts[66][68];
    int bc_ = blockIdx.x;
    int c = bc_ & 3, b = bc_ >> 2;
    int t = threadIdx.x;
    for (int i = t; i < 66 * 68; i += 256) ((float*)ts)[i] = 0.f;
    __syncthreads();
    const float* xb = xin + b * 16 * 16 * 64 + c * 16;
#pragma unroll
    for (int it = 0; it < 16; it++) {
        int e = it * 256 + t;
        int pq = e >> 4, ij = e & 15;
        int p = pq >> 4, q = pq & 15;
        int i2 = ij >> 2, j2 = ij & 3;
        ts[1 + p * 4 + i2][1 + q * 4 + j2] = xb[pq * 64 + ij];
    }
    __syncthreads();
    float wr[9];
#pragma unroll
    for (int i = 0; i < 9; i++) wr[i] = __ldg(&cw[c * 9 + i]);
    float cbv = __ldg(&cb[c]);
    int h = t >> 2, wq = t & 3;
    float* op = xc + (bc_ * 64 + h) * 64 + wq * 16;
#pragma unroll
    for (int j = 0; j < 16; j++) {
        int wcol = wq * 16 + j;
        float acc = cbv;
#pragma unroll
        for (int di = 0; di < 3; di++)
#pragma unroll
            for (int dj = 0; dj < 3; dj++)
                acc += ts[h + di][wcol + dj] * wr[di * 3 + dj];
        op[j] = silu(acc);
    }
}

// ---------------- K2b: patch conv + BN ---------------------------------------
__global__ void __launch_bounds__(512) k_patch(const float* __restrict__ xc,
                                               const float* __restrict__ pw,
                                               const float* __restrict__ pb,
                                               const float* __restrict__ gam,
                                               const float* __restrict__ bet,
                                               const float* __restrict__ mn,
                                               const float* __restrict__ vr,
                                               float* __restrict__ xt) {
    __shared__ __align__(16) float ws[64 * 65];
    __shared__ __align__(16) float px[64][64];
    int b = blockIdx.y, lg = blockIdx.x;
    int e = threadIdx.x, li = threadIdx.y;
    int t = li * 64 + e;
    for (int i = t; i < 4096; i += 512) ws[(i & 63) * 65 + (i >> 6)] = pw[i];
    for (int i = t; i < 4096; i += 512) {
        int row = i >> 6, m = i & 63;
        int l = lg * 64 + row;
        int ph = l >> 4, pwd = l & 15;
        int c = m >> 4, ij = m & 15, i2 = ij >> 2, j2 = ij & 3;
        px[row][m] = xc[((b * 4 + c) * 64 + ph * 4 + i2) * 64 + pwd * 4 + j2];
    }
    __syncthreads();
    float acc[8];
#pragma unroll
    for (int j = 0; j < 8; j++) acc[j] = 0.f;
    int r0 = li * 8;
#pragma unroll
    for (int m4 = 0; m4 < 16; m4++) {
        float4 xv[8];
#pragma unroll
        for (int j = 0; j < 8; j++) xv[j] = ((const float4*)px[r0 + j])[m4];
#pragma unroll
        for (int dd = 0; dd < 4; dd++) {
            float wv = ws[(m4 * 4 + dd) * 65 + e];
#pragma unroll
            for (int j = 0; j < 8; j++) {
                float v = dd == 0 ? xv[j].x : dd == 1 ? xv[j].y : dd == 2 ? xv[j].z : xv[j].w;
                acc[j] += v * wv;
            }
        }
    }
    float sc = __ldg(&gam[e]) * rsqrtf(__ldg(&vr[e]) + 1e-5f);
    float pbv = __ldg(&pb[e]), mnv = __ldg(&mn[e]), btv = __ldg(&bet[e]);
#pragma unroll
    for (int j = 0; j < 8; j++)
        xt[(b * 256 + lg * 64 + r0 + j) * 64 + e] = (acc[j] + pbv - mnv) * sc + btv;
}

// ---------------- K3: x_dbl projection via tf32 mma --------------------------
// grid (4, B), 256 threads = 8 warps. C[l][c] = X[l][kk] * W[c][kk].
// As: tf32 [kk][l], stride 264 (==8 mod 32 -> conflict-free frag loads)
// Bs: tf32 [kk][c], stride 72  (==8 mod 32)
// Warp w: M-tiles rows [w*32, w*32+32), 9 N-tiles (c 0..71), 8 k-steps.
#define AS_STRIDE 264
#define BS_STRIDE 72
__global__ void __launch_bounds__(256) k_proj(const float* __restrict__ xt,
                                              const float* __restrict__ xpw,
                                              float* __restrict__ dtrg,
                                              float* __restrict__ bc) {
    extern __shared__ unsigned sm[];
    unsigned* As = sm;                     // 64 * 264
    unsigned* Bs = sm + 64 * AS_STRIDE;    // 64 * 72
    int k = blockIdx.x, b = blockIdx.y;
    int t = threadIdx.x, w = t >> 5, lane = t & 31;
    int gid = lane >> 2, tig = lane & 3;
    const float* wk = xpw + k * CPROJ * 64;

    // stage B: Bs[kk][c]
    for (int i = t; i < CPROJ * 64; i += 256) {
        int c = i >> 6, kk = i & 63;
        Bs[kk * BS_STRIDE + c] = f2tf(wk[i]);
    }
    // stage A: thread t stages row t (gathered): As[kk][t]
    {
        int lm = map_l(k, t);
        const float4* xp = (const float4*)(xt + (b * 256 + lm) * 64);
#pragma unroll
        for (int j4 = 0; j4 < 16; j4++) {
            float4 v = __ldg(xp + j4);
            As[(4 * j4 + 0) * AS_STRIDE + t] = f2tf(v.x);
            As[(4 * j4 + 1) * AS_STRIDE + t] = f2tf(v.y);
            As[(4 * j4 + 2) * AS_STRIDE + t] = f2tf(v.z);
            As[(4 * j4 + 3) * AS_STRIDE + t] = f2tf(v.w);
        }
    }
    __syncthreads();

    float acc[2][9][4];
#pragma unroll
    for (int mi = 0; mi < 2; mi++)
#pragma unroll
        for (int n = 0; n < 9; n++)
#pragma unroll
            for (int q = 0; q < 4; q++) acc[mi][n][q] = 0.f;

    int r0 = w * 32;
#pragma unroll
    for (int ks = 0; ks < 8; ks++) {
        int kb = ks * 8;
        unsigned a[2][4];
#pragma unroll
        for (int mi = 0; mi < 2; mi++) {
            int r = r0 + mi * 16;
            a[mi][0] = As[(kb + tig) * AS_STRIDE + r + gid];
            a[mi][1] = As[(kb + tig) * AS_STRIDE + r + gid + 8];
            a[mi][2] = As[(kb + tig + 4) * AS_STRIDE + r + gid];
            a[mi][3] = As[(kb + tig + 4) * AS_STRIDE + r + gid + 8];
        }
#pragma unroll
        for (int n = 0; n < 9; n++) {
            unsigned b0 = Bs[(kb + tig) * BS_STRIDE + n * 8 + gid];
            unsigned b1 = Bs[(kb + tig + 4) * BS_STRIDE + n * 8 + gid];
            mma_tf32(acc[0][n], a[0][0], a[0][1], a[0][2], a[0][3], b0, b1);
            mma_tf32(acc[1][n], a[1][0], a[1][1], a[1][2], a[1][3], b0, b1);
        }
    }

    float* dto = dtrg + (b * 4 + k) * NST * 256;
    float* bco = bc + (b * 4 + k) * 48 * 256;
#pragma unroll
    for (int mi = 0; mi < 2; mi++) {
        int rbase = r0 + mi * 16 + gid;
#pragma unroll
        for (int n = 0; n < 9; n++) {
            int c0 = n * 8 + 2 * tig;
#pragma unroll
            for (int q = 0; q < 2; q++) {
                int c = c0 + q;
                float vlo = acc[mi][n][q];
                float vhi = acc[mi][n][q + 2];
                if (c < 24) {
                    dto[c * 256 + rbase]     = vlo;
                    dto[c * 256 + rbase + 8] = vhi;
                } else {
                    bco[(c - 24) * 256 + rbase]     = vlo;
                    bco[(c - 24) * 256 + rbase + 8] = vhi;
                }
            }
        }
    }
}
#define PROJ_SMEM ((64 * AS_STRIDE + 64 * BS_STRIDE) * 4)

// ---------------- K4: scan with fused dt projection --------------------------
__global__ void __launch_bounds__(64) k_scan(const float* __restrict__ xt,
                                             const float* __restrict__ dtrg,
                                             const float* __restrict__ bc,
                                             const float* __restrict__ dtw_g,
                                             const float* __restrict__ alog,
                                             const float* __restrict__ dbias,
                                             const float* __restrict__ Dsv,
                                             float* __restrict__ yg) {
    __shared__ __align__(8) float sbc[16][48];
    __shared__ __align__(8) float sdtr[NST * 16];
    __shared__ float su[16][64];
    int k = blockIdx.x, b = blockIdx.y;
    int d = threadIdx.x;
    int kd = k * 64 + d;

    float dtw[NST];
    {
        const float4* dwp = (const float4*)(dtw_g + kd * NST);
#pragma unroll
        for (int i = 0; i < 6; i++) {
            float4 v = __ldg(dwp + i);
            dtw[4 * i] = v.x; dtw[4 * i + 1] = v.y;
            dtw[4 * i + 2] = v.z; dtw[4 * i + 3] = v.w;
        }
    }
    float a0 = -__expf(__ldg(&alog[kd * NST]));
    bool chain = (a0 != 0.f);
#pragma unroll
    for (int n = 1; n < NST; n++) {
        float an = -__expf(__ldg(&alog[kd * NST + n]));
        chain = chain && (fabsf(an - (float)(n + 1) * a0) <= 1e-4f * fabsf(an));
    }
    float bias = __ldg(&dbias[kd]);
    float Dv = __ldg(&Dsv[kd]);
    int kb = b * 4 + k;
    const float* dtrp = dtrg + kb * NST * 256;
    const float* bcp = bc + kb * 48 * 256;
    const float* xrow = xt + b * 256 * 64;
    float* yp = yg + kb * 256 * 64;

    u64 h2[12];
#pragma unroll
    for (int p = 0; p < 12; p++) h2[p] = 0ull;

    for (int l0 = 0; l0 < 256; l0 += 16) {
        __syncthreads();
#pragma unroll
        for (int m = 0; m < 12; m++) {
            int idx = d * 12 + m;
            sbc[idx & 15][idx >> 4] = bcp[(idx >> 4) * 256 + l0 + (idx & 15)];
        }
#pragma unroll
        for (int m = 0; m < 6; m++) {
            int idx = d * 6 + m;
            sdtr[idx] = dtrp[(idx >> 4) * 256 + l0 + (idx & 15)];
        }
#pragma unroll
        for (int i = 0; i < 16; i++)
            su[i][d] = __ldg(&xrow[map_l(k, l0 + i) * 64 + d]);
        __syncthreads();

        float dtc[16];
        {
            u64 dt2[8];
#pragma unroll
            for (int ip = 0; ip < 8; ip++) dt2[ip] = 0ull;
#pragma unroll
            for (int r = 0; r < NST; r++) {
                u64 wp = pk2(dtw[r], dtw[r]);
#pragma unroll
                for (int ip = 0; ip < 8; ip++)
                    dt2[ip] = fma2(wp, *(const u64*)&sdtr[r * 16 + 2 * ip], dt2[ip]);
            }
#pragma unroll
            for (int ip = 0; ip < 8; ip++) unpk2(dtc[2 * ip], dtc[2 * ip + 1], dt2[ip]);
        }

        if (chain) {
#pragma unroll 2
            for (int i = 0; i < 16; i++) {
                int l = l0 + i;
                float xv = dtc[i] + bias;
                float delta = (xv > 15.f) ? xv : __logf(1.f + __expf(xv));
                float u = su[i][d];
                float du = delta * u;
                float q = __expf(delta * a0);
                float q2s = q * q, q4s = q2s * q2s, q8s = q4s * q4s, q16s = q8s * q8s;
                u64 Q2 = pk2(q2s, q2s), Q4 = pk2(q4s, q4s);
                u64 Q8 = pk2(q8s, q8s), Q16 = pk2(q16s, q16s);
                u64 P[12];
                P[0] = pk2(q, q2s);
                P[1] = mul2(P[0], Q2);
                P[2] = mul2(P[0], Q4);  P[3] = mul2(P[1], Q4);
                P[4] = mul2(P[0], Q8);  P[5] = mul2(P[1], Q8);
                P[6] = mul2(P[2], Q8);  P[7] = mul2(P[3], Q8);
                P[8] = mul2(P[0], Q16); P[9] = mul2(P[1], Q16);
                P[10] = mul2(P[2], Q16); P[11] = mul2(P[3], Q16);
                u64 du2 = pk2(du, du);
                u64 y2 = 0ull;
#pragma unroll
                for (int p = 0; p < 12; p++) {
                    u64 B2 = *(const u64*)&sbc[i][2 * p];
                    u64 C2 = *(const u64*)&sbc[i][24 + 2 * p];
                    h2[p] = fma2(P[p], h2[p], mul2(du2, B2));
                    y2 = fma2(h2[p], C2, y2);
                }
                float ylo, yhi;
                unpk2(ylo, yhi, y2);
                yp[map_l(k, l) * 64 + d] = ylo + yhi + Dv * u;
            }
        } else {
#pragma unroll 1
            for (int i = 0; i < 16; i++) {
                int l = l0 + i;
                float xv = dtc[i] + bias;
                float delta = (xv > 15.f) ? xv : __logf(1.f + __expf(xv));
                float u = su[i][d];
                float du = delta * u;
                u64 du2 = pk2(du, du);
                u64 y2 = 0ull;
#pragma unroll
                for (int p = 0; p < 12; p++) {
                    float alo = -__expf(__ldg(&alog[kd * NST + 2 * p]));
                    float ahi = -__expf(__ldg(&alog[kd * NST + 2 * p + 1]));
                    u64 dA = pk2(__expf(delta * alo), __expf(delta * ahi));
                    u64 B2 = *(const u64*)&sbc[i][2 * p];
                    u64 C2 = *(const u64*)&sbc[i][24 + 2 * p];
                    h2[p] = fma2(dA, h2[p], mul2(du2, B2));
                    y2 = fma2(h2[p], C2, y2);
                }
                float ylo, yhi;
                unpk2(ylo, yhi, y2);
                yp[map_l(k, l) * 64 + d] = ylo + yhi + Dv * u;
            }
        }
    }
}

// ---------------- K5: combine + LN + gate + out_proj -------------------------
__global__ void __launch_bounds__(128) k_final(const float* __restrict__ yg,
                                               const float* __restrict__ zg,
                                               const float* __restrict__ lng,
                                               const float* __restrict__ lnb,
                                               const float* __restrict__ wo,
                                               float* __restrict__ out) {
    __shared__ __align__(16) float ws[64 * 68];
    __shared__ float gs[64], bs[64];
    int b = blockIdx.y, half = blockIdx.x;
    int tid = threadIdx.x;
    int l = half * 128 + tid;
    for (int i = tid; i < 4096; i += 128) {
        int dd = i >> 6, ee = i & 63;
        ws[ee * 68 + dd] = wo[i];
    }
    if (tid < 64) { gs[tid] = lng[tid]; bs[tid] = lnb[tid]; }
    __syncthreads();
    int b4 = b * 4;
    const float4* y0 = (const float4*)(yg + ((b4 + 0) * 256 + l) * 64);
    const float4* y1 = (const float4*)(yg + ((b4 + 1) * 256 + l) * 64);
    const float4* y2 = (const float4*)(yg + ((b4 + 2) * 256 + l) * 64);
    const float4* y3 = (const float4*)(yg + ((b4 + 3) * 256 + l) * 64);
    float yv[64];
    float mu = 0.f;
#pragma unroll
    for (int i = 0; i < 16; i++) {
        float4 v0 = y0[i], v1 = y1[i], v2 = y2[i], v3 = y3[i];
        yv[4 * i + 0] = v0.x + v1.x + v2.x + v3.x;
        yv[4 * i + 1] = v0.y + v1.y + v2.y + v3.y;
        yv[4 * i + 2] = v0.z + v1.z + v2.z + v3.z;
        yv[4 * i + 3] = v0.w + v1.w + v2.w + v3.w;
        mu += yv[4 * i] + yv[4 * i + 1] + yv[4 * i + 2] + yv[4 * i + 3];
    }
    mu *= (1.f / 64.f);
    float var = 0.f;
#pragma unroll
    for (int e = 0; e < 64; e++) {
        float tv = yv[e] - mu;
        var += tv * tv;
    }
    var *= (1.f / 64.f);
    float rs = rsqrtf(var + 1e-5f);
    const float4* zp = (const float4*)(zg + (b * 256 + l) * 64);
#pragma unroll
    for (int i = 0; i < 16; i++) {
        float4 zv = zp[i];
        yv[4 * i + 0] = ((yv[4 * i + 0] - mu) * rs * gs[4 * i + 0] + bs[4 * i + 0]) * zv.x;
        yv[4 * i + 1] = ((yv[4 * i + 1] - mu) * rs * gs[4 * i + 1] + bs[4 * i + 1]) * zv.y;
        yv[4 * i + 2] = ((yv[4 * i + 2] - mu) * rs * gs[4 * i + 2] + bs[4 * i + 2]) * zv.z;
        yv[4 * i + 3] = ((yv[4 * i + 3] - mu) * rs * gs[4 * i + 3] + bs[4 * i + 3]) * zv.w;
    }
    float4* op = (float4*)(out + (b * 256 + l) * 64);
#pragma unroll 1
    for (int dc = 0; dc < 16; dc++) {
        float4 acc = {0.f, 0.f, 0.f, 0.f};
#pragma unroll
        for (int e = 0; e < 64; e++) {
            float4 w4 = *(const float4*)&ws[e * 68 + dc * 4];
            acc.x += yv[e] * w4.x;
            acc.y += yv[e] * w4.y;
            acc.z += yv[e] * w4.z;
            acc.w += yv[e] * w4.w;
        }
        op[dc] = acc;
    }
}

// ---------------- launch ------------------------------------------------------
extern "C" void kernel_launch(void* const* d_in, const int* in_sizes, int n_in,
                              void* d_out, int out_size) {
    const float* x_in   = (const float*)d_in[0];
    const float* ipw    = (const float*)d_in[1];
    const float* conv_w = (const float*)d_in[2];
    const float* conv_b = (const float*)d_in[3];
    const float* patch_w= (const float*)d_in[4];
    const float* patch_b= (const float*)d_in[5];
    const float* bn_g   = (const float*)d_in[6];
    const float* bn_b   = (const float*)d_in[7];
    const float* bn_m   = (const float*)d_in[8];
    const float* bn_v   = (const float*)d_in[9];
    const float* xpw    = (const float*)d_in[10];
    const float* dtw    = (const float*)d_in[11];
    const float* dtb    = (const float*)d_in[12];
    const float* alog   = (const float*)d_in[13];
    const float* Dsv    = (const float*)d_in[14];
    const float* lng    = (const float*)d_in[15];
    const float* lnb    = (const float*)d_in[16];
    const float* wo     = (const float*)d_in[17];
    float* out = (float*)d_out;

    float *zg, *xc, *xt, *dtrg, *bcv, *yg;
    cudaGetSymbolAddress((void**)&zg,   g_z);
    cudaGetSymbolAddress((void**)&xc,   g_xconv);
    cudaGetSymbolAddress((void**)&xt,   g_xt);
    cudaGetSymbolAddress((void**)&dtrg, g_dtr);
    cudaGetSymbolAddress((void**)&bcv,  g_bc);
    cudaGetSymbolAddress((void**)&yg,   g_y);

    cudaFuncSetAttribute(k_proj, cudaFuncAttributeMaxDynamicSharedMemorySize,
                         PROJ_SMEM);

    dim3 blk64_8(64, 8);
    k_zproj<<<dim3(4, BATCH), blk64_8>>>(x_in, ipw, zg);
    k_dwconv<<<BATCH * 4, 256>>>(x_in, conv_w, conv_b, xc);
    k_patch<<<dim3(4, BATCH), blk64_8>>>(xc, patch_w, patch_b,
                                         bn_g, bn_b, bn_m, bn_v, xt);
    k_proj<<<dim3(4, BATCH), 256, PROJ_SMEM>>>(xt, xpw, dtrg, bcv);
    k_scan<<<dim3(4, BATCH), 64>>>(xt, dtrg, bcv, dtw, alog, dtb, Dsv, yg);
    k_final<<<dim3(2, BATCH), 128>>>(yg, zg, lng, lnb, wo, out);
}

// round 6
// speedup vs baseline: 3.8197x; 1.0557x over previous
#include <cuda_runtime.h>
#include <cuda_bf16.h>

#define BATCH 256
#define L 256
#define D 64
#define NST 24
#define CPROJ 72   // DT_RANK + 2*NST

typedef unsigned long long u64;

// ---------------- scratch ----------------------------------------------------
__device__ float g_xconv[BATCH * 4 * 64 * 64];  // (b,c,h,w)
__device__ float g_xt[BATCH * L * D];           // (b,l,d)
__device__ float g_dtr[BATCH * 4 * NST * L];    // (b,k,r,l)
__device__ float g_bc[BATCH * 4 * 48 * L];      // (b,k,j,l)  j:0..23=B, 24..47=C
__device__ float g_ysum[BATCH * L * D];         // combined y (b,l,d)

__device__ __forceinline__ int map_l(int k, int l) {
    int lm = (k & 2) ? (255 - l) : l;
    if (k & 1) lm = ((lm & 15) << 4) | (lm >> 4);
    return lm;
}
__device__ __forceinline__ float silu(float x) { return x / (1.f + __expf(-x)); }

__device__ __forceinline__ u64 pk2(float lo, float hi) {
    u64 r; asm("mov.b64 %0,{%1,%2};" : "=l"(r) : "f"(lo), "f"(hi)); return r;
}
__device__ __forceinline__ void unpk2(float& lo, float& hi, u64 v) {
    asm("mov.b64 {%0,%1},%2;" : "=f"(lo), "=f"(hi) : "l"(v));
}
__device__ __forceinline__ u64 mul2(u64 a, u64 b) {
    u64 r; asm("mul.rn.f32x2 %0,%1,%2;" : "=l"(r) : "l"(a), "l"(b)); return r;
}
__device__ __forceinline__ u64 fma2(u64 a, u64 b, u64 c) {
    u64 r; asm("fma.rn.f32x2 %0,%1,%2,%3;" : "=l"(r) : "l"(a), "l"(b), "l"(c)); return r;
}
__device__ __forceinline__ unsigned f2tf(float f) {
    unsigned u; asm("cvt.rna.tf32.f32 %0,%1;" : "=r"(u) : "f"(f)); return u;
}
__device__ __forceinline__ void mma_tf32(float c[4],
                                         unsigned a0, unsigned a1, unsigned a2, unsigned a3,
                                         unsigned b0, unsigned b1) {
    asm volatile(
        "mma.sync.aligned.m16n8k8.row.col.f32.tf32.tf32.f32 "
        "{%0,%1,%2,%3},{%4,%5,%6,%7},{%8,%9},{%0,%1,%2,%3};"
        : "+f"(c[0]), "+f"(c[1]), "+f"(c[2]), "+f"(c[3])
        : "r"(a0), "r"(a1), "r"(a2), "r"(a3), "r"(b0), "r"(b1));
}

// ---------------- K2a: depthwise conv ----------------------------------------
__global__ void __launch_bounds__(256) k_dwconv(const float* __restrict__ xin,
                                                const float* __restrict__ cw,
                                                const float* __restrict__ cb,
                                                float* __restrict__ xc) {
    __shared__ float ts[66][68];
    int bc_ = blockIdx.x;
    int c = bc_ & 3, b = bc_ >> 2;
    int t = threadIdx.x;
    for (int i = t; i < 66 * 68; i += 256) ((float*)ts)[i] = 0.f;
    __syncthreads();
    const float* xb = xin + b * 16 * 16 * 64 + c * 16;
#pragma unroll
    for (int it = 0; it < 16; it++) {
        int e = it * 256 + t;
        int pq = e >> 4, ij = e & 15;
        int p = pq >> 4, q = pq & 15;
        int i2 = ij >> 2, j2 = ij & 3;
        ts[1 + p * 4 + i2][1 + q * 4 + j2] = xb[pq * 64 + ij];
    }
    __syncthreads();
    float wr[9];
#pragma unroll
    for (int i = 0; i < 9; i++) wr[i] = __ldg(&cw[c * 9 + i]);
    float cbv = __ldg(&cb[c]);
    int h = t >> 2, wq = t & 3;
    float* op = xc + (bc_ * 64 + h) * 64 + wq * 16;
#pragma unroll
    for (int j = 0; j < 16; j++) {
        int wcol = wq * 16 + j;
        float acc = cbv;
#pragma unroll
        for (int di = 0; di < 3; di++)
#pragma unroll
            for (int dj = 0; dj < 3; dj++)
                acc += ts[h + di][wcol + dj] * wr[di * 3 + dj];
        op[j] = silu(acc);
    }
}

// ---------------- K2b: patch conv + BN ---------------------------------------
__global__ void __launch_bounds__(512) k_patch(const float* __restrict__ xc,
                                               const float* __restrict__ pw,
                                               const float* __restrict__ pb,
                                               const float* __restrict__ gam,
                                               const float* __restrict__ bet,
                                               const float* __restrict__ mn,
                                               const float* __restrict__ vr,
                                               float* __restrict__ xt) {
    __shared__ __align__(16) float ws[64 * 65];
    __shared__ __align__(16) float px[64][64];
    int b = blockIdx.y, lg = blockIdx.x;
    int e = threadIdx.x, li = threadIdx.y;
    int t = li * 64 + e;
    for (int i = t; i < 4096; i += 512) ws[(i & 63) * 65 + (i >> 6)] = pw[i];
    for (int i = t; i < 4096; i += 512) {
        int row = i >> 6, m = i & 63;
        int l = lg * 64 + row;
        int ph = l >> 4, pwd = l & 15;
        int c = m >> 4, ij = m & 15, i2 = ij >> 2, j2 = ij & 3;
        px[row][m] = xc[((b * 4 + c) * 64 + ph * 4 + i2) * 64 + pwd * 4 + j2];
    }
    __syncthreads();
    float acc[8];
#pragma unroll
    for (int j = 0; j < 8; j++) acc[j] = 0.f;
    int r0 = li * 8;
#pragma unroll
    for (int m4 = 0; m4 < 16; m4++) {
        float4 xv[8];
#pragma unroll
        for (int j = 0; j < 8; j++) xv[j] = ((const float4*)px[r0 + j])[m4];
#pragma unroll
        for (int dd = 0; dd < 4; dd++) {
            float wv = ws[(m4 * 4 + dd) * 65 + e];
#pragma unroll
            for (int j = 0; j < 8; j++) {
                float v = dd == 0 ? xv[j].x : dd == 1 ? xv[j].y : dd == 2 ? xv[j].z : xv[j].w;
                acc[j] += v * wv;
            }
        }
    }
    float sc = __ldg(&gam[e]) * rsqrtf(__ldg(&vr[e]) + 1e-5f);
    float pbv = __ldg(&pb[e]), mnv = __ldg(&mn[e]), btv = __ldg(&bet[e]);
#pragma unroll
    for (int j = 0; j < 8; j++)
        xt[(b * 256 + lg * 64 + r0 + j) * 64 + e] = (acc[j] + pbv - mnv) * sc + btv;
}

// ---------------- K3: x_dbl projection via tf32 mma (low-reg, 2 CTA/SM) ------
#define AS_STRIDE 264
#define BS_STRIDE 72
__global__ void __launch_bounds__(256, 2) k_proj(const float* __restrict__ xt,
                                                 const float* __restrict__ xpw,
                                                 float* __restrict__ dtrg,
                                                 float* __restrict__ bc) {
    extern __shared__ unsigned sm[];
    unsigned* As = sm;                     // 64 * 264
    unsigned* Bs = sm + 64 * AS_STRIDE;    // 64 * 72
    int k = blockIdx.x, b = blockIdx.y;
    int t = threadIdx.x, w = t >> 5, lane = t & 31;
    int gid = lane >> 2, tig = lane & 3;
    const float* wk = xpw + k * CPROJ * 64;

    for (int i = t; i < CPROJ * 64; i += 256) {
        int c = i >> 6, kk = i & 63;
        Bs[kk * BS_STRIDE + c] = f2tf(wk[i]);
    }
    {
        int lm = map_l(k, t);
        const float4* xp = (const float4*)(xt + (b * 256 + lm) * 64);
#pragma unroll
        for (int j4 = 0; j4 < 16; j4++) {
            float4 v = __ldg(xp + j4);
            As[(4 * j4 + 0) * AS_STRIDE + t] = f2tf(v.x);
            As[(4 * j4 + 1) * AS_STRIDE + t] = f2tf(v.y);
            As[(4 * j4 + 2) * AS_STRIDE + t] = f2tf(v.z);
            As[(4 * j4 + 3) * AS_STRIDE + t] = f2tf(v.w);
        }
    }
    __syncthreads();

    int r0 = w * 32;
    // load all A fragments once (64 regs), loop N outside
    unsigned a[8][2][4];
#pragma unroll
    for (int ks = 0; ks < 8; ks++) {
        int kb = ks * 8;
#pragma unroll
        for (int mi = 0; mi < 2; mi++) {
            int r = r0 + mi * 16;
            a[ks][mi][0] = As[(kb + tig) * AS_STRIDE + r + gid];
            a[ks][mi][1] = As[(kb + tig) * AS_STRIDE + r + gid + 8];
            a[ks][mi][2] = As[(kb + tig + 4) * AS_STRIDE + r + gid];
            a[ks][mi][3] = As[(kb + tig + 4) * AS_STRIDE + r + gid + 8];
        }
    }

    float* dto = dtrg + (b * 4 + k) * NST * 256;
    float* bco = bc + (b * 4 + k) * 48 * 256;
#pragma unroll
    for (int n = 0; n < 9; n++) {
        float acc0[4] = {0.f, 0.f, 0.f, 0.f};
        float acc1[4] = {0.f, 0.f, 0.f, 0.f};
#pragma unroll
        for (int ks = 0; ks < 8; ks++) {
            int kb = ks * 8;
            unsigned b0 = Bs[(kb + tig) * BS_STRIDE + n * 8 + gid];
            unsigned b1 = Bs[(kb + tig + 4) * BS_STRIDE + n * 8 + gid];
            mma_tf32(acc0, a[ks][0][0], a[ks][0][1], a[ks][0][2], a[ks][0][3], b0, b1);
            mma_tf32(acc1, a[ks][1][0], a[ks][1][1], a[ks][1][2], a[ks][1][3], b0, b1);
        }
        int c0 = n * 8 + 2 * tig;
#pragma unroll
        for (int q = 0; q < 2; q++) {
            int c = c0 + q;
            float* base = (c < 24) ? (dto + c * 256) : (bco + (c - 24) * 256);
            base[r0 + gid]          = acc0[q];
            base[r0 + gid + 8]      = acc0[q + 2];
            base[r0 + 16 + gid]     = acc1[q];
            base[r0 + 16 + gid + 8] = acc1[q + 2];
        }
    }
}
#define PROJ_SMEM ((64 * AS_STRIDE + 64 * BS_STRIDE) * 4)

// ---------------- K4: scan, fused dt proj, atomic combine ---------------------
__global__ void __launch_bounds__(64) k_scan(const float* __restrict__ xt,
                                             const float* __restrict__ dtrg,
                                             const float* __restrict__ bc,
                                             const float* __restrict__ dtw_g,
                                             const float* __restrict__ alog,
                                             const float* __restrict__ dbias,
                                             const float* __restrict__ Dsv,
                                             float* __restrict__ ysum) {
    __shared__ __align__(8) float sbc[16][48];
    __shared__ __align__(8) float sdtr[NST * 16];
    __shared__ float su[16][64];
    int k = blockIdx.x, b = blockIdx.y;
    int d = threadIdx.x;
    int kd = k * 64 + d;

    float dtw[NST];
    {
        const float4* dwp = (const float4*)(dtw_g + kd * NST);
#pragma unroll
        for (int i = 0; i < 6; i++) {
            float4 v = __ldg(dwp + i);
            dtw[4 * i] = v.x; dtw[4 * i + 1] = v.y;
            dtw[4 * i + 2] = v.z; dtw[4 * i + 3] = v.w;
        }
    }
    float a0 = -__expf(__ldg(&alog[kd * NST]));
    bool chain = (a0 != 0.f);
#pragma unroll
    for (int n = 1; n < NST; n++) {
        float an = -__expf(__ldg(&alog[kd * NST + n]));
        chain = chain && (fabsf(an - (float)(n + 1) * a0) <= 1e-4f * fabsf(an));
    }
    float bias = __ldg(&dbias[kd]);
    float Dv = __ldg(&Dsv[kd]);
    int kb = b * 4 + k;
    const float* dtrp = dtrg + kb * NST * 256;
    const float* bcp = bc + kb * 48 * 256;
    const float* xrow = xt + b * 256 * 64;
    float* yb = ysum + b * 256 * 64;

    u64 h2[12];
#pragma unroll
    for (int p = 0; p < 12; p++) h2[p] = 0ull;

    for (int l0 = 0; l0 < 256; l0 += 16) {
        __syncthreads();
#pragma unroll
        for (int m = 0; m < 12; m++) {
            int idx = d * 12 + m;
            sbc[idx & 15][idx >> 4] = bcp[(idx >> 4) * 256 + l0 + (idx & 15)];
        }
#pragma unroll
        for (int m = 0; m < 6; m++) {
            int idx = d * 6 + m;
            sdtr[idx] = dtrp[(idx >> 4) * 256 + l0 + (idx & 15)];
        }
#pragma unroll
        for (int i = 0; i < 16; i++)
            su[i][d] = __ldg(&xrow[map_l(k, l0 + i) * 64 + d]);
        __syncthreads();

        float dtc[16];
        {
            u64 dt2[8];
#pragma unroll
            for (int ip = 0; ip < 8; ip++) dt2[ip] = 0ull;
#pragma unroll
            for (int r = 0; r < NST; r++) {
                u64 wp = pk2(dtw[r], dtw[r]);
#pragma unroll
                for (int ip = 0; ip < 8; ip++)
                    dt2[ip] = fma2(wp, *(const u64*)&sdtr[r * 16 + 2 * ip], dt2[ip]);
            }
#pragma unroll
            for (int ip = 0; ip < 8; ip++) unpk2(dtc[2 * ip], dtc[2 * ip + 1], dt2[ip]);
        }

        if (chain) {
#pragma unroll 2
            for (int i = 0; i < 16; i++) {
                int l = l0 + i;
                float xv = dtc[i] + bias;
                float delta = (xv > 15.f) ? xv : __logf(1.f + __expf(xv));
                float u = su[i][d];
                float du = delta * u;
                float q = __expf(delta * a0);
                float q2s = q * q, q4s = q2s * q2s, q8s = q4s * q4s, q16s = q8s * q8s;
                u64 Q2 = pk2(q2s, q2s), Q4 = pk2(q4s, q4s);
                u64 Q8 = pk2(q8s, q8s), Q16 = pk2(q16s, q16s);
                u64 P[12];
                P[0] = pk2(q, q2s);
                P[1] = mul2(P[0], Q2);
                P[2] = mul2(P[0], Q4);  P[3] = mul2(P[1], Q4);
                P[4] = mul2(P[0], Q8);  P[5] = mul2(P[1], Q8);
                P[6] = mul2(P[2], Q8);  P[7] = mul2(P[3], Q8);
                P[8] = mul2(P[0], Q16); P[9] = mul2(P[1], Q16);
                P[10] = mul2(P[2], Q16); P[11] = mul2(P[3], Q16);
                u64 du2 = pk2(du, du);
                u64 y2a = 0ull, y2b = 0ull;
#pragma unroll
                for (int p = 0; p < 12; p++) {
                    u64 B2 = *(const u64*)&sbc[i][2 * p];
                    u64 C2 = *(const u64*)&sbc[i][24 + 2 * p];
                    h2[p] = fma2(P[p], h2[p], mul2(du2, B2));
                    if (p & 1) y2b = fma2(h2[p], C2, y2b);
                    else       y2a = fma2(h2[p], C2, y2a);
                }
                float ylo, yhi, zlo, zhi;
                unpk2(ylo, yhi, y2a); unpk2(zlo, zhi, y2b);
                atomicAdd(&yb[map_l(k, l) * 64 + d], ylo + yhi + zlo + zhi + Dv * u);
            }
        } else {
#pragma unroll 1
            for (int i = 0; i < 16; i++) {
                int l = l0 + i;
                float xv = dtc[i] + bias;
                float delta = (xv > 15.f) ? xv : __logf(1.f + __expf(xv));
                float u = su[i][d];
                float du = delta * u;
                u64 du2 = pk2(du, du);
                u64 y2 = 0ull;
#pragma unroll
                for (int p = 0; p < 12; p++) {
                    float alo = -__expf(__ldg(&alog[kd * NST + 2 * p]));
                    float ahi = -__expf(__ldg(&alog[kd * NST + 2 * p + 1]));
                    u64 dA = pk2(__expf(delta * alo), __expf(delta * ahi));
                    u64 B2 = *(const u64*)&sbc[i][2 * p];
                    u64 C2 = *(const u64*)&sbc[i][24 + 2 * p];
                    h2[p] = fma2(dA, h2[p], mul2(du2, B2));
                    y2 = fma2(h2[p], C2, y2);
                }
                float ylo, yhi;
                unpk2(ylo, yhi, y2);
                atomicAdd(&yb[map_l(k, l) * 64 + d], ylo + yhi + Dv * u);
            }
        }
    }
}

// ---------------- K5: LN + inline z-gate + out_proj ---------------------------
// grid (B), block 256: thread per l. z computed inline from x_in.
__global__ void __launch_bounds__(256) k_final(const float* __restrict__ xin,
                                               const float* __restrict__ ysum,
                                               const float* __restrict__ ipw,
                                               const float* __restrict__ lng,
                                               const float* __restrict__ lnb,
                                               const float* __restrict__ wo,
                                               float* __restrict__ out) {
    __shared__ __align__(16) float wsI[64 * 64];  // in_proj [e][d]
    __shared__ __align__(16) float wsO[64 * 64];  // out_proj [dd][e]
    __shared__ float gs[64], bs[64];
    int b = blockIdx.x, l = threadIdx.x;
    for (int i = l; i < 4096; i += 256) { wsI[i] = ipw[i]; wsO[i] = wo[i]; }
    if (l < 64) { gs[l] = lng[l]; bs[l] = lnb[l]; }
    __syncthreads();

    float yv[64];
    u64 xr2[32];
    float mu = 0.f;
    {
        const float4* yp = (const float4*)(ysum + (b * 256 + l) * 64);
        const float4* xp = (const float4*)(xin + (b * 256 + l) * 64);
#pragma unroll
        for (int i = 0; i < 16; i++) {
            float4 v = yp[i];
            yv[4 * i + 0] = v.x; yv[4 * i + 1] = v.y;
            yv[4 * i + 2] = v.z; yv[4 * i + 3] = v.w;
            mu += v.x + v.y + v.z + v.w;
            float4 x = xp[i];
            xr2[2 * i]     = pk2(x.x, x.y);
            xr2[2 * i + 1] = pk2(x.z, x.w);
        }
    }
    mu *= (1.f / 64.f);
    float var = 0.f;
#pragma unroll
    for (int e = 0; e < 64; e++) { float tv = yv[e] - mu; var += tv * tv; }
    var *= (1.f / 64.f);
    float rs = rsqrtf(var + 1e-5f);

    // gated row: g[e] = LN(yv)[e] * silu(x_in . Win[e])
    u64 g2[32];
#pragma unroll
    for (int e2 = 0; e2 < 32; e2++) {
        float ge[2];
#pragma unroll
        for (int h = 0; h < 2; h++) {
            int e = 2 * e2 + h;
            const u64* wrow = (const u64*)&wsI[e * 64];
            u64 acc = 0ull;
#pragma unroll
            for (int j = 0; j < 32; j++) acc = fma2(xr2[j], wrow[j], acc);
            float lo, hi; unpk2(lo, hi, acc);
            float zv = silu(lo + hi);
            ge[h] = ((yv[e] - mu) * rs * gs[e] + bs[e]) * zv;
        }
        g2[e2] = pk2(ge[0], ge[1]);
    }

    // out[l][dd] = sum_e g[e] * Wo[dd][e], 4 dd at a time -> float4 store
    float4* op = (float4*)(out + (b * 256 + l) * 64);
#pragma unroll 1
    for (int dg = 0; dg < 16; dg++) {
        float res[4];
#pragma unroll
        for (int q = 0; q < 4; q++) {
            const u64* wrow = (const u64*)&wsO[(dg * 4 + q) * 64];
            u64 acc = 0ull;
#pragma unroll
            for (int j = 0; j < 32; j++) acc = fma2(g2[j], wrow[j], acc);
            float lo, hi; unpk2(lo, hi, acc);
            res[q] = lo + hi;
        }
        op[dg] = make_float4(res[0], res[1], res[2], res[3]);
    }
}

// ---------------- launch ------------------------------------------------------
extern "C" void kernel_launch(void* const* d_in, const int* in_sizes, int n_in,
                              void* d_out, int out_size) {
    const float* x_in   = (const float*)d_in[0];
    const float* ipw    = (const float*)d_in[1];
    const float* conv_w = (const float*)d_in[2];
    const float* conv_b = (const float*)d_in[3];
    const float* patch_w= (const float*)d_in[4];
    const float* patch_b= (const float*)d_in[5];
    const float* bn_g   = (const float*)d_in[6];
    const float* bn_b   = (const float*)d_in[7];
    const float* bn_m   = (const float*)d_in[8];
    const float* bn_v   = (const float*)d_in[9];
    const float* xpw    = (const float*)d_in[10];
    const float* dtw    = (const float*)d_in[11];
    const float* dtb    = (const float*)d_in[12];
    const float* alog   = (const float*)d_in[13];
    const float* Dsv    = (const float*)d_in[14];
    const float* lng    = (const float*)d_in[15];
    const float* lnb    = (const float*)d_in[16];
    const float* wo     = (const float*)d_in[17];
    float* out = (float*)d_out;

    float *xc, *xt, *dtrg, *bcv, *ysum;
    cudaGetSymbolAddress((void**)&xc,   g_xconv);
    cudaGetSymbolAddress((void**)&xt,   g_xt);
    cudaGetSymbolAddress((void**)&dtrg, g_dtr);
    cudaGetSymbolAddress((void**)&bcv,  g_bc);
    cudaGetSymbolAddress((void**)&ysum, g_ysum);

    cudaFuncSetAttribute(k_proj, cudaFuncAttributeMaxDynamicSharedMemorySize,
                         PROJ_SMEM);

    cudaMemsetAsync(ysum, 0, (size_t)BATCH * L * D * sizeof(float));

    dim3 blk64_8(64, 8);
    k_dwconv<<<BATCH * 4, 256>>>(x_in, conv_w, conv_b, xc);
    k_patch<<<dim3(4, BATCH), blk64_8>>>(xc, patch_w, patch_b,
                                         bn_g, bn_b, bn_m, bn_v, xt);
    k_proj<<<dim3(4, BATCH), 256, PROJ_SMEM>>>(xt, xpw, dtrg, bcv);
    k_scan<<<dim3(4, BATCH), 64>>>(xt, dtrg, bcv, dtw, alog, dtb, Dsv, ysum);
    k_final<<<BATCH, 256>>>(x_in, ysum, ipw, lng, lnb, wo, out);
}